// round 1
// baseline (speedup 1.0000x reference)
#include <cuda_runtime.h>
#include <math.h>

// ---------------- problem constants ----------------
#define T_TOK 8192      // B*L
#define DIMD  1024
#define DIMH  2048
#define NEXP  8
#define TOPK  2
#define NITEM (T_TOK*TOPK)   // 16384 dispatched rows
#define NBLK_DISP 64         // dispatch blocks (256 items each)

// ---------------- scratch (device globals: no allocation allowed) ----------------
__device__ float g_h1[(size_t)T_TOK * DIMH];    // gate hidden, then reused as shared-expert hidden (64 MB)
__device__ float g_he[(size_t)NITEM * DIMH];    // expert hidden, compacted dispatch rows (128 MB)
__device__ int   g_topk_idx[NITEM];             // [T][2] expert ids
__device__ float g_topk_w[NITEM];               // [T][2] softmax weights
__device__ int   g_list[NITEM];                 // token id per dispatch slot
__device__ float g_wlist[NITEM];                // gate weight per dispatch slot
__device__ int   g_cnt[NEXP];
__device__ int   g_base[NEXP];
__device__ int   g_blockCnt[NBLK_DISP * NEXP];
__device__ int   g_blockOff[NBLK_DISP * NEXP];

// ---------------- activations ----------------
__device__ __forceinline__ float gelu_erf(float v) {
    return 0.5f * v * (1.0f + erff(v * 0.70710678118654752f));
}
__device__ __forceinline__ float gelu_tanh(float v) {
    float u = 0.7978845608028654f * (v + 0.044715f * v * v * v);
    // tanh(u) = 1 - 2/(exp(2u)+1); __expf/__fdividef handle +-inf saturation correctly
    float t = __expf(2.0f * u);
    float th = 1.0f - __fdividef(2.0f, t + 1.0f);
    return 0.5f * v * (1.0f + th);
}

// ---------------- SGEMM 128x128x8, 256 threads, 8x8 per thread ----------------
// MODE 0: dense A, dense C store
// MODE 1: gather A rows via g_list (A=x), store C into g_he at compacted rows (masked by cnt)
// MODE 2: dense A within expert region (A=g_he), atomic scatter C += w * (acc+bias) into out
// ACT  0: none, 1: erf-gelu, 2: tanh-gelu
#define BM 128
#define BN 128
#define BK 8
#define TM 8
#define TN 8

template<int ACT, int MODE>
__global__ __launch_bounds__(256, 2)
void sgemm(const float* __restrict__ Abase,
           const float* __restrict__ Bbase,
           const float* __restrict__ biasBase,
           float* __restrict__ C,
           int M, int N, int K)
{
    const int e  = blockIdx.z;
    const int m0 = blockIdx.x * BM;
    const int n0 = blockIdx.y * BN;

    int base = 0, cnt = M;
    const float* B    = Bbase;
    const float* bias = biasBase;
    if (MODE != 0) {
        base = g_base[e];
        cnt  = g_cnt[e];
        if (m0 >= cnt) return;                       // uniform per block
        B    = Bbase    + (size_t)e * K * N;
        bias = biasBase + (size_t)e * N;
    }

    __shared__ float As[BK][BM];
    __shared__ float Bs[BK][BN];

    const int tid  = threadIdx.x;
    const int aRow = tid >> 1;           // 0..127
    const int aCol = (tid & 1) * 4;      // 0 or 4
    const int bRow = tid >> 5;           // 0..7
    const int bCol = (tid & 31) * 4;     // 0..124

    // resolve A row pointer once (gather does not depend on k)
    const float* Arow;
    if (MODE == 1) {
        int m  = m0 + aRow;
        int mm = (m < cnt) ? m : 0;
        int tok = g_list[base + mm];
        Arow = Abase + (size_t)tok * K;
    } else if (MODE == 2) {
        int m  = m0 + aRow;
        int mm = (m < cnt) ? m : 0;
        Arow = Abase + (size_t)(base + mm) * K;
    } else {
        Arow = Abase + (size_t)(m0 + aRow) * K;
    }
    const float* Bp = B + (size_t)bRow * N + n0 + bCol;

    const int ty = tid >> 4, tx = tid & 15;
    float acc[TM][TN];
#pragma unroll
    for (int i = 0; i < TM; i++)
#pragma unroll
        for (int j = 0; j < TN; j++) acc[i][j] = 0.f;

    for (int k0 = 0; k0 < K; k0 += BK) {
        float4 av = *reinterpret_cast<const float4*>(Arow + k0 + aCol);
        As[aCol + 0][aRow] = av.x;
        As[aCol + 1][aRow] = av.y;
        As[aCol + 2][aRow] = av.z;
        As[aCol + 3][aRow] = av.w;
        float4 bv = *reinterpret_cast<const float4*>(Bp + (size_t)k0 * N);
        *reinterpret_cast<float4*>(&Bs[bRow][bCol]) = bv;
        __syncthreads();

#pragma unroll
        for (int kk = 0; kk < BK; kk++) {
            float4 a0 = *reinterpret_cast<const float4*>(&As[kk][ty * TM]);
            float4 a1 = *reinterpret_cast<const float4*>(&As[kk][ty * TM + 4]);
            float4 b0 = *reinterpret_cast<const float4*>(&Bs[kk][tx * TN]);
            float4 b1 = *reinterpret_cast<const float4*>(&Bs[kk][tx * TN + 4]);
            float a[TM] = {a0.x, a0.y, a0.z, a0.w, a1.x, a1.y, a1.z, a1.w};
            float b[TN] = {b0.x, b0.y, b0.z, b0.w, b1.x, b1.y, b1.z, b1.w};
#pragma unroll
            for (int i = 0; i < TM; i++)
#pragma unroll
                for (int j = 0; j < TN; j++)
                    acc[i][j] = fmaf(a[i], b[j], acc[i][j]);
        }
        __syncthreads();
    }

    // epilogue
    const int cRow0 = m0 + ty * TM;
    const int cCol0 = n0 + tx * TN;
    float bvreg[TN];
#pragma unroll
    for (int j = 0; j < TN; j++) bvreg[j] = bias[cCol0 + j];

#pragma unroll
    for (int i = 0; i < TM; i++) {
        int m = cRow0 + i;
        if (MODE != 0 && m >= cnt) continue;
        int tok = 0; float w = 0.f;
        if (MODE == 2) { tok = g_list[base + m]; w = g_wlist[base + m]; }
#pragma unroll
        for (int j = 0; j < TN; j++) {
            float v = acc[i][j] + bvreg[j];
            if (ACT == 1) v = gelu_erf(v);
            if (ACT == 2) v = gelu_tanh(v);
            if (MODE == 0)      C[(size_t)m * N + cCol0 + j] = v;
            else if (MODE == 1) C[(size_t)(base + m) * N + cCol0 + j] = v;
            else                atomicAdd(C + (size_t)tok * N + cCol0 + j, w * v);
        }
    }
}

// ---------------- logits (h1 @ gw2 + gb2) + softmax + top-2, fused ----------------
__global__ void logits_topk(const float* __restrict__ h1,
                            const float* __restrict__ gw2,
                            const float* __restrict__ gb2)
{
    const int t = blockIdx.x;
    const float* hrow = h1 + (size_t)t * DIMH;
    float acc[NEXP];
#pragma unroll
    for (int j = 0; j < NEXP; j++) acc[j] = 0.f;

    for (int i = threadIdx.x; i < DIMH; i += 256) {
        float h = hrow[i];
        float4 w0 = *reinterpret_cast<const float4*>(gw2 + (size_t)i * NEXP);
        float4 w1 = *reinterpret_cast<const float4*>(gw2 + (size_t)i * NEXP + 4);
        acc[0] = fmaf(h, w0.x, acc[0]); acc[1] = fmaf(h, w0.y, acc[1]);
        acc[2] = fmaf(h, w0.z, acc[2]); acc[3] = fmaf(h, w0.w, acc[3]);
        acc[4] = fmaf(h, w1.x, acc[4]); acc[5] = fmaf(h, w1.y, acc[5]);
        acc[6] = fmaf(h, w1.z, acc[6]); acc[7] = fmaf(h, w1.w, acc[7]);
    }

    const int lane = threadIdx.x & 31, wid = threadIdx.x >> 5;
#pragma unroll
    for (int j = 0; j < NEXP; j++)
#pragma unroll
        for (int o = 16; o > 0; o >>= 1)
            acc[j] += __shfl_down_sync(0xffffffffu, acc[j], o);

    __shared__ float red[8][NEXP];
    if (lane == 0) {
#pragma unroll
        for (int j = 0; j < NEXP; j++) red[wid][j] = acc[j];
    }
    __syncthreads();

    if (threadIdx.x == 0) {
        float l[NEXP];
#pragma unroll
        for (int j = 0; j < NEXP; j++) {
            l[j] = gb2[j];
#pragma unroll
            for (int wdx = 0; wdx < 8; wdx++) l[j] += red[wdx][j];
        }
        float mx = l[0];
#pragma unroll
        for (int j = 1; j < NEXP; j++) mx = fmaxf(mx, l[j]);
        float p[NEXP], s = 0.f;
#pragma unroll
        for (int j = 0; j < NEXP; j++) { p[j] = expf(l[j] - mx); s += p[j]; }
        float inv = 1.0f / s;
#pragma unroll
        for (int j = 0; j < NEXP; j++) p[j] *= inv;

        int i0 = 0;
#pragma unroll
        for (int j = 1; j < NEXP; j++) if (p[j] > p[i0]) i0 = j;   // first max on ties (jax top_k)
        int i1 = (i0 == 0) ? 1 : 0;
#pragma unroll
        for (int j = 0; j < NEXP; j++) if (j != i0 && p[j] > p[i1]) i1 = j;

        g_topk_idx[t * 2 + 0] = i0;  g_topk_w[t * 2 + 0] = p[i0];
        g_topk_idx[t * 2 + 1] = i1;  g_topk_w[t * 2 + 1] = p[i1];
    }
}

// ---------------- deterministic dispatch: count / scan / rank+write ----------------
__global__ void dispatch_count() {
    __shared__ int scnt[NEXP];
    if (threadIdx.x < NEXP) scnt[threadIdx.x] = 0;
    __syncthreads();
    int item = blockIdx.x * 256 + threadIdx.x;       // item = token*2 + k
    int e = g_topk_idx[item];
    atomicAdd(&scnt[e], 1);
    __syncthreads();
    if (threadIdx.x < NEXP) g_blockCnt[blockIdx.x * NEXP + threadIdx.x] = scnt[threadIdx.x];
}

__global__ void dispatch_scan() {
    int e = threadIdx.x;
    if (e < NEXP) {
        int off = 0;
        for (int b = 0; b < NBLK_DISP; b++) {
            g_blockOff[b * NEXP + e] = off;
            off += g_blockCnt[b * NEXP + e];
        }
        g_cnt[e] = off;
    }
    __syncthreads();
    if (threadIdx.x == 0) {
        int base = 0;
        for (int e2 = 0; e2 < NEXP; e2++) { g_base[e2] = base; base += g_cnt[e2]; }
    }
}

__global__ void dispatch_write() {
    __shared__ int se[256];
    const int i = threadIdx.x;
    const int item = blockIdx.x * 256 + i;
    const int e = g_topk_idx[item];
    se[i] = e;
    __syncthreads();
    int rank = 0;
    for (int j = 0; j < i; j++) rank += (se[j] == e);
    int pos = g_base[e] + g_blockOff[blockIdx.x * NEXP + e] + rank;
    g_list[pos]  = item >> 1;         // token id
    g_wlist[pos] = g_topk_w[item];
}

// ---------------- launch ----------------
extern "C" void kernel_launch(void* const* d_in, const int* in_sizes, int n_in,
                              void* d_out, int out_size)
{
    const float* x   = (const float*)d_in[0];
    // d_in[1] = task_ids (unused by reference math)
    const float* gw1 = (const float*)d_in[2];
    const float* gb1 = (const float*)d_in[3];
    const float* gw2 = (const float*)d_in[4];
    const float* gb2 = (const float*)d_in[5];
    const float* We1 = (const float*)d_in[6];
    const float* be1 = (const float*)d_in[7];
    const float* We2 = (const float*)d_in[8];
    const float* be2 = (const float*)d_in[9];
    const float* Ws1 = (const float*)d_in[10];
    const float* bs1 = (const float*)d_in[11];
    const float* Ws2 = (const float*)d_in[12];
    const float* bs2 = (const float*)d_in[13];
    float* out = (float*)d_out;

    float *h1, *he;
    cudaGetSymbolAddress((void**)&h1, g_h1);
    cudaGetSymbolAddress((void**)&he, g_he);

    // 1) gate hidden: h1 = gelu_erf(x @ gw1 + gb1)                [8192,2048]
    sgemm<1,0><<<dim3(T_TOK/BM, DIMH/BN, 1), 256>>>(x, gw1, gb1, h1, T_TOK, DIMH, DIMD);
    // 2) logits + softmax + top2
    logits_topk<<<T_TOK, 256>>>(h1, gw2, gb2);
    // 3) deterministic dispatch
    dispatch_count<<<NBLK_DISP, 256>>>();
    dispatch_scan<<<1, 32>>>();
    dispatch_write<<<NBLK_DISP, 256>>>();
    // 4) shared expert (reuse h1)
    sgemm<2,0><<<dim3(T_TOK/BM, DIMH/BN, 1), 256>>>(x, Ws1, bs1, h1, T_TOK, DIMH, DIMD);
    sgemm<0,0><<<dim3(T_TOK/BM, DIMD/BN, 1), 256>>>(h1, Ws2, bs2, out, T_TOK, DIMD, DIMH);
    // 5) routed experts: gathered GEMM1 -> he, then GEMM2 scatter-add into out
    sgemm<2,1><<<dim3(T_TOK/BM, DIMH/BN, NEXP), 256>>>(x,  We1, be1, he,  0, DIMH, DIMD);
    sgemm<0,2><<<dim3(T_TOK/BM, DIMD/BN, NEXP), 256>>>(he, We2, be2, out, 0, DIMD, DIMH);
}

// round 3
// speedup vs baseline: 3.7397x; 3.7397x over previous
#include <cuda_runtime.h>
#include <cuda_fp16.h>
#include <cstdint>
#include <math.h>

// ---------------- problem constants ----------------
#define T_TOK 8192
#define DIMD  1024
#define DIMH  2048
#define NEXP  8
#define NITEM (T_TOK*2)
#define NBLK_DISP 64
#define LO_SCALE 256.0f
#define INV_LO_SCALE (1.0f/256.0f)

// ---------------- scratch (device globals) ----------------
__device__ float  g_h1[(size_t)T_TOK * DIMH];           // gate hidden, fp32 (routing precision)
__device__ __half g_hs[(size_t)T_TOK * DIMH];           // shared-expert hidden fp16
__device__ __half g_he[(size_t)NITEM * DIMH];           // routed hidden fp16 (compact)
__device__ __half g_xhi[(size_t)T_TOK * DIMD];
__device__ __half g_xlo[(size_t)T_TOK * DIMD];          // (x - xhi) * 256
__device__ __half g_Bg1h[(size_t)DIMH * DIMD];          // gw1^T hi
__device__ __half g_Bg1l[(size_t)DIMH * DIMD];          // gw1^T lo*256
__device__ __half g_Bs1h[(size_t)DIMH * DIMD];
__device__ __half g_Bs2h[(size_t)DIMD * DIMH];
__device__ __half g_Be1h[(size_t)NEXP * DIMH * DIMD];
__device__ __half g_Be2h[(size_t)NEXP * DIMD * DIMH];
__device__ int    g_topk_idx[NITEM];
__device__ float  g_topk_w[NITEM];
__device__ int    g_list[NITEM];
__device__ float  g_wlist[NITEM];
__device__ int    g_cnt[NEXP];
__device__ int    g_base[NEXP];
__device__ int    g_mblkBase[NEXP + 1];
__device__ int    g_blockCnt[NBLK_DISP * NEXP];
__device__ int    g_blockOff[NBLK_DISP * NEXP];

// ---------------- PTX helpers (baseline sm_80+ features only) ----------------
__device__ __forceinline__ uint32_t smem_u32(const void* p) {
    uint32_t a;
    asm("{ .reg .u64 t; cvta.to.shared.u64 t, %1; cvt.u32.u64 %0, t; }" : "=r"(a) : "l"(p));
    return a;
}
__device__ __forceinline__ void ldsm4(uint32_t& r0, uint32_t& r1, uint32_t& r2, uint32_t& r3, uint32_t a) {
    asm volatile("ldmatrix.sync.aligned.m8n8.x4.shared.b16 {%0,%1,%2,%3}, [%4];"
                 : "=r"(r0), "=r"(r1), "=r"(r2), "=r"(r3) : "r"(a));
}
__device__ __forceinline__ void mma16816(float* d, const uint32_t* a, const uint32_t* b) {
    asm volatile("mma.sync.aligned.m16n8k16.row.col.f32.f16.f16.f32 "
                 "{%0,%1,%2,%3},{%4,%5,%6,%7},{%8,%9},{%0,%1,%2,%3};"
                 : "+f"(d[0]), "+f"(d[1]), "+f"(d[2]), "+f"(d[3])
                 : "r"(a[0]), "r"(a[1]), "r"(a[2]), "r"(a[3]), "r"(b[0]), "r"(b[1]));
}
#define CP_ASYNC16(sa, ga) asm volatile("cp.async.cg.shared.global [%0], [%1], 16;" :: "r"(sa), "l"(ga))
#define CP_COMMIT()        asm volatile("cp.async.commit_group;" ::: "memory")
#define CP_WAIT1()         asm volatile("cp.async.wait_group 1;"  ::: "memory")
#define CP_WAIT0()         asm volatile("cp.async.wait_group 0;"  ::: "memory")

// ---------------- activations ----------------
__device__ __forceinline__ float gelu_erf(float v) {
    return 0.5f * v * (1.0f + erff(v * 0.70710678118654752f));
}
__device__ __forceinline__ float gelu_tanh(float v) {
    float u = 0.7978845608028654f * (v + 0.044715f * v * v * v);
    float t = __expf(2.0f * u);
    float th = 1.0f - __fdividef(2.0f, t + 1.0f);
    return 0.5f * v * (1.0f + th);
}

// ---------------- conversions ----------------
__global__ void cvt_hilo(const float* __restrict__ src, __half* __restrict__ hi,
                         __half* __restrict__ lo, int n4) {
    int i = blockIdx.x * blockDim.x + threadIdx.x;
    if (i >= n4) return;
    float4 v = reinterpret_cast<const float4*>(src)[i];
    __half h0 = __float2half_rn(v.x), h1 = __float2half_rn(v.y);
    __half h2 = __float2half_rn(v.z), h3 = __float2half_rn(v.w);
    __half2* hp = reinterpret_cast<__half2*>(hi) + 2 * i;
    hp[0] = __halves2half2(h0, h1); hp[1] = __halves2half2(h2, h3);
    __half l0 = __float2half_rn((v.x - __half2float(h0)) * LO_SCALE);
    __half l1 = __float2half_rn((v.y - __half2float(h1)) * LO_SCALE);
    __half l2 = __float2half_rn((v.z - __half2float(h2)) * LO_SCALE);
    __half l3 = __float2half_rn((v.w - __half2float(h3)) * LO_SCALE);
    __half2* lp = reinterpret_cast<__half2*>(lo) + 2 * i;
    lp[0] = __halves2half2(l0, l1); lp[1] = __halves2half2(l2, l3);
}

// transpose [R,C] fp32 -> [C,R] fp16 (optionally lo*256), batched z
template<bool LO>
__global__ void transpose_cvt(const float* __restrict__ src, __half* __restrict__ dhi,
                              __half* __restrict__ dlo, int R, int C) {
    __shared__ float t[32][33];
    size_t zs = (size_t)blockIdx.z * R * C;
    int c0 = blockIdx.x * 32, r0 = blockIdx.y * 32;
    int x = threadIdx.x, y = threadIdx.y;
#pragma unroll
    for (int dy = 0; dy < 32; dy += 8)
        t[y + dy][x] = src[zs + (size_t)(r0 + y + dy) * C + c0 + x];
    __syncthreads();
#pragma unroll
    for (int dy = 0; dy < 32; dy += 8) {
        float v = t[x][y + dy];
        size_t o = zs + (size_t)(c0 + y + dy) * R + r0 + x;
        __half h = __float2half_rn(v);
        dhi[o] = h;
        if (LO) dlo[o] = __float2half_rn((v - __half2float(h)) * LO_SCALE);
    }
}

// ---------------- fp16 tensor GEMM: CTA 128x128, BK=64, 2-stage cp.async ----------------
// MODE 0: dense A rows; 1: gather A rows via g_list (expert blocks); 2: dense compact A, atomic scatter
// ACT 0: none, 1: gelu_erf, 2: gelu_tanh
// OUT 0: fp32 store, 1: fp16 store, 2: fp32 atomicAdd weighted
#define ROWPAD 72                     // halves per smem row (144B: conflict-free ldmatrix)
#define TILE_P (128 * ROWPAD * 2)     // 18432 B
#define STAGE_E (2 * TILE_P)          // A + B
#define SME_BYTES (2 * STAGE_E)       // 73728

template<int MODE, int ACT, int OUT>
__global__ __launch_bounds__(256)
void gemm_f16(const __half* __restrict__ A, const __half* __restrict__ Bt,
              const float* __restrict__ bias, void* __restrict__ Cv,
              int K, int ldc)
{
    int e = 0, m0, base = 0, cnt = 0;
    const int Nfull = gridDim.y * 128;
    if (MODE == 0) {
        m0 = blockIdx.x * 128;
    } else {
        if ((int)blockIdx.x >= g_mblkBase[NEXP]) return;
#pragma unroll
        for (int i = 1; i < NEXP; i++) if ((int)blockIdx.x >= g_mblkBase[i]) e = i;
        m0 = ((int)blockIdx.x - g_mblkBase[e]) * 128;
        base = g_base[e]; cnt = g_cnt[e];
        Bt   += (size_t)e * Nfull * K;
        bias += (size_t)e * Nfull;
    }
    const int n0 = blockIdx.y * 128;

    extern __shared__ char smem[];
    const uint32_t sbase = smem_u32(smem);
    const int tid = threadIdx.x, lane = tid & 31, wid = tid >> 5;

    // ---- load geometry: 4 A rows + 4 B rows per thread, 16B chunk col (tid&7)
    const int lrow = tid >> 3;
    const uint32_t dstOff = (uint32_t)(lrow * 144 + (tid & 7) * 16);
    const __half* aptr[4];
#pragma unroll
    for (int i = 0; i < 4; i++) {
        int m = m0 + lrow + 32 * i;
        if (MODE == 0)      aptr[i] = A + (size_t)m * K;
        else if (MODE == 1) { int mm = (m < cnt) ? m : 0; aptr[i] = A + (size_t)g_list[base + mm] * K; }
        else                { int mm = (m < cnt) ? m : 0; aptr[i] = A + (size_t)(base + mm) * K; }
        aptr[i] += (tid & 7) * 8;
    }
    const __half* bptr[4];
#pragma unroll
    for (int i = 0; i < 4; i++)
        bptr[i] = Bt + (size_t)(n0 + lrow + 32 * i) * K + (tid & 7) * 8;

    const int S = K >> 6;
    // prologue: stage 0
    {
        uint32_t sA = sbase, sB = sbase + TILE_P;
#pragma unroll
        for (int i = 0; i < 4; i++) CP_ASYNC16(sA + dstOff + (uint32_t)(32 * i * 144), (const void*)aptr[i]);
#pragma unroll
        for (int i = 0; i < 4; i++) CP_ASYNC16(sB + dstOff + (uint32_t)(32 * i * 144), (const void*)bptr[i]);
        CP_COMMIT();
    }

    // ---- compute-lane constants
    const int wm0 = (wid >> 1) * 32;
    const int wn0 = (wid & 1) * 64;
    const int arow_l = (lane & 7) + ((lane >> 3) & 1) * 8;
    const int acol_l = (lane >> 4) * 8;
    const int brow_l = (lane >> 4) * 8 + (lane & 7);
    const int bcol_l = ((lane >> 3) & 1) * 8;

    float acc[2][8][4];
#pragma unroll
    for (int i = 0; i < 2; i++)
#pragma unroll
        for (int j = 0; j < 8; j++)
#pragma unroll
            for (int q = 0; q < 4; q++) acc[i][j][q] = 0.f;

    for (int s = 0; s < S; s++) {
        if (s + 1 < S) {
            uint32_t st = sbase + (uint32_t)(((s + 1) & 1) * STAGE_E);
            uint32_t sA = st, sB = st + TILE_P;
#pragma unroll
            for (int i = 0; i < 4; i++) CP_ASYNC16(sA + dstOff + (uint32_t)(32 * i * 144), (const void*)(aptr[i] + (s + 1) * 64));
#pragma unroll
            for (int i = 0; i < 4; i++) CP_ASYNC16(sB + dstOff + (uint32_t)(32 * i * 144), (const void*)(bptr[i] + (s + 1) * 64));
            CP_COMMIT();
            CP_WAIT1();
        } else {
            CP_WAIT0();
        }
        __syncthreads();

        const uint32_t st = sbase + (uint32_t)((s & 1) * STAGE_E);
        const uint32_t sA = st, sB = st + TILE_P;
#pragma unroll
        for (int ks = 0; ks < 4; ks++) {
            const int k0 = ks * 16;
            uint32_t a[2][4], b[4][4];
#pragma unroll
            for (int mf = 0; mf < 2; mf++)
                ldsm4(a[mf][0], a[mf][1], a[mf][2], a[mf][3],
                      sA + (uint32_t)((wm0 + mf * 16 + arow_l) * 144 + (k0 + acol_l) * 2));
#pragma unroll
            for (int p = 0; p < 4; p++)
                ldsm4(b[p][0], b[p][1], b[p][2], b[p][3],
                      sB + (uint32_t)((wn0 + p * 16 + brow_l) * 144 + (k0 + bcol_l) * 2));
#pragma unroll
            for (int mf = 0; mf < 2; mf++)
#pragma unroll
                for (int nf = 0; nf < 8; nf++)
                    mma16816(acc[mf][nf], a[mf], &b[nf >> 1][(nf & 1) * 2]);
        }
        __syncthreads();
    }

    // ---- epilogue ----
    const int tr = lane >> 2, tc = (lane & 3) * 2;
#pragma unroll
    for (int mf = 0; mf < 2; mf++) {
#pragma unroll
        for (int half_ = 0; half_ < 2; half_++) {
            const int m = m0 + wm0 + mf * 16 + tr + half_ * 8;
            const bool valid = (MODE == 0) || (m - m0 + (m0 - m0)) < 0x7fffffff; // placeholder
            int mloc = m;                 // block-local == global row for MODE0
            bool ok = true;
            int orow = m; float wgt = 0.f;
            if (MODE != 0) {
                ok = (m < cnt);
                if (ok) {
                    if (MODE == 1) orow = base + m;
                    else { orow = g_list[base + m]; wgt = g_wlist[base + m]; }
                }
            }
            (void)valid; (void)mloc;
            if (!ok) continue;
#pragma unroll
            for (int nf = 0; nf < 8; nf++) {
                const int c = n0 + wn0 + nf * 8 + tc;
                float v0 = acc[mf][nf][half_ * 2 + 0] + bias[c];
                float v1 = acc[mf][nf][half_ * 2 + 1] + bias[c + 1];
                if (ACT == 1) { v0 = gelu_erf(v0);  v1 = gelu_erf(v1); }
                if (ACT == 2) { v0 = gelu_tanh(v0); v1 = gelu_tanh(v1); }
                if (OUT == 0) {
                    float2 w2; w2.x = v0; w2.y = v1;
                    *reinterpret_cast<float2*>((float*)Cv + (size_t)orow * ldc + c) = w2;
                } else if (OUT == 1) {
                    *reinterpret_cast<__half2*>((__half*)Cv + (size_t)orow * ldc + c) =
                        __halves2half2(__float2half_rn(v0), __float2half_rn(v1));
                } else {
                    float* cp = (float*)Cv + (size_t)orow * ldc + c;
                    atomicAdd(cp + 0, wgt * v0);
                    atomicAdd(cp + 1, wgt * v1);
                }
            }
        }
    }
}

// ---------------- gate GEMM: 3-pass hi/lo fp16, CTA 128x64, BK=64, fp32 out ----------------
#define TILE_B64 (64 * ROWPAD * 2)    // 9216
#define STAGE_G (2 * TILE_P + 2 * TILE_B64)  // 55296
#define SMG_BYTES (2 * STAGE_G)       // 110592

__global__ __launch_bounds__(256)
void gemm_gate(const __half* __restrict__ Ahi, const __half* __restrict__ Alo,
               const __half* __restrict__ Bhi, const __half* __restrict__ Blo,
               const float* __restrict__ bias, float* __restrict__ C, int K)
{
    const int m0 = blockIdx.x * 128;
    const int n0 = blockIdx.y * 64;

    extern __shared__ char smem[];
    const uint32_t sbase = smem_u32(smem);
    const int tid = threadIdx.x, lane = tid & 31, wid = tid >> 5;

    const int lrow = tid >> 3;
    const uint32_t dstOff = (uint32_t)(lrow * 144 + (tid & 7) * 16);
    const __half *ah[4], *al[4];
#pragma unroll
    for (int i = 0; i < 4; i++) {
        size_t ro = (size_t)(m0 + lrow + 32 * i) * K + (tid & 7) * 8;
        ah[i] = Ahi + ro; al[i] = Alo + ro;
    }
    const __half *bh[2], *bl[2];
#pragma unroll
    for (int i = 0; i < 2; i++) {
        size_t ro = (size_t)(n0 + lrow + 32 * i) * K + (tid & 7) * 8;
        bh[i] = Bhi + ro; bl[i] = Blo + ro;
    }

    const int S = K >> 6;
    // stage layout: AHI@0, ALO@TILE_P, BHI@2*TILE_P, BLO@2*TILE_P+TILE_B64
    auto issue = [&](int s) {
        uint32_t st = sbase + (uint32_t)((s & 1) * STAGE_G);
#pragma unroll
        for (int i = 0; i < 4; i++) CP_ASYNC16(st + dstOff + (uint32_t)(32 * i * 144), (const void*)(ah[i] + s * 64));
#pragma unroll
        for (int i = 0; i < 4; i++) CP_ASYNC16(st + TILE_P + dstOff + (uint32_t)(32 * i * 144), (const void*)(al[i] + s * 64));
#pragma unroll
        for (int i = 0; i < 2; i++) CP_ASYNC16(st + 2 * TILE_P + dstOff + (uint32_t)(32 * i * 144), (const void*)(bh[i] + s * 64));
#pragma unroll
        for (int i = 0; i < 2; i++) CP_ASYNC16(st + 2 * TILE_P + TILE_B64 + dstOff + (uint32_t)(32 * i * 144), (const void*)(bl[i] + s * 64));
        CP_COMMIT();
    };
    issue(0);

    const int wm0 = (wid >> 1) * 32;
    const int wn0 = (wid & 1) * 32;
    const int arow_l = (lane & 7) + ((lane >> 3) & 1) * 8;
    const int acol_l = (lane >> 4) * 8;
    const int brow_l = (lane >> 4) * 8 + (lane & 7);
    const int bcol_l = ((lane >> 3) & 1) * 8;

    float acc1[2][4][4], acc2[2][4][4];
#pragma unroll
    for (int i = 0; i < 2; i++)
#pragma unroll
        for (int j = 0; j < 4; j++)
#pragma unroll
            for (int q = 0; q < 4; q++) { acc1[i][j][q] = 0.f; acc2[i][j][q] = 0.f; }

    for (int s = 0; s < S; s++) {
        if (s + 1 < S) { issue(s + 1); CP_WAIT1(); } else { CP_WAIT0(); }
        __syncthreads();
        const uint32_t st = sbase + (uint32_t)((s & 1) * STAGE_G);
#pragma unroll
        for (int ks = 0; ks < 4; ks++) {
            const int k0 = ks * 16;
            uint32_t ahr[2][4], alr[2][4], bhr[2][4], blr[2][4];
#pragma unroll
            for (int mf = 0; mf < 2; mf++) {
                uint32_t ao = (uint32_t)((wm0 + mf * 16 + arow_l) * 144 + (k0 + acol_l) * 2);
                ldsm4(ahr[mf][0], ahr[mf][1], ahr[mf][2], ahr[mf][3], st + ao);
                ldsm4(alr[mf][0], alr[mf][1], alr[mf][2], alr[mf][3], st + TILE_P + ao);
            }
#pragma unroll
            for (int p = 0; p < 2; p++) {
                uint32_t bo = (uint32_t)((wn0 + p * 16 + brow_l) * 144 + (k0 + bcol_l) * 2);
                ldsm4(bhr[p][0], bhr[p][1], bhr[p][2], bhr[p][3], st + 2 * TILE_P + bo);
                ldsm4(blr[p][0], blr[p][1], blr[p][2], blr[p][3], st + 2 * TILE_P + TILE_B64 + bo);
            }
#pragma unroll
            for (int mf = 0; mf < 2; mf++)
#pragma unroll
                for (int nf = 0; nf < 4; nf++) {
                    const uint32_t* bhp = &bhr[nf >> 1][(nf & 1) * 2];
                    const uint32_t* blp = &blr[nf >> 1][(nf & 1) * 2];
                    mma16816(acc1[mf][nf], ahr[mf], bhp);
                    mma16816(acc2[mf][nf], ahr[mf], blp);
                    mma16816(acc2[mf][nf], alr[mf], bhp);
                }
        }
        __syncthreads();
    }

    const int tr = lane >> 2, tc = (lane & 3) * 2;
#pragma unroll
    for (int mf = 0; mf < 2; mf++)
#pragma unroll
        for (int half_ = 0; half_ < 2; half_++) {
            const int m = m0 + wm0 + mf * 16 + tr + half_ * 8;
#pragma unroll
            for (int nf = 0; nf < 4; nf++) {
                const int c = n0 + wn0 + nf * 8 + tc;
                float v0 = acc1[mf][nf][half_ * 2 + 0] + acc2[mf][nf][half_ * 2 + 0] * INV_LO_SCALE + bias[c];
                float v1 = acc1[mf][nf][half_ * 2 + 1] + acc2[mf][nf][half_ * 2 + 1] * INV_LO_SCALE + bias[c + 1];
                float2 w2; w2.x = gelu_erf(v0); w2.y = gelu_erf(v1);
                *reinterpret_cast<float2*>(C + (size_t)m * DIMH + c) = w2;
            }
        }
}

// ---------------- logits + softmax + top-2 (fp32) ----------------
__global__ void logits_topk(const float* __restrict__ h1,
                            const float* __restrict__ gw2,
                            const float* __restrict__ gb2)
{
    const int t = blockIdx.x;
    const float* hrow = h1 + (size_t)t * DIMH;
    float acc[NEXP];
#pragma unroll
    for (int j = 0; j < NEXP; j++) acc[j] = 0.f;
    for (int i = threadIdx.x; i < DIMH; i += 256) {
        float h = hrow[i];
        float4 w0 = *reinterpret_cast<const float4*>(gw2 + (size_t)i * NEXP);
        float4 w1 = *reinterpret_cast<const float4*>(gw2 + (size_t)i * NEXP + 4);
        acc[0] = fmaf(h, w0.x, acc[0]); acc[1] = fmaf(h, w0.y, acc[1]);
        acc[2] = fmaf(h, w0.z, acc[2]); acc[3] = fmaf(h, w0.w, acc[3]);
        acc[4] = fmaf(h, w1.x, acc[4]); acc[5] = fmaf(h, w1.y, acc[5]);
        acc[6] = fmaf(h, w1.z, acc[6]); acc[7] = fmaf(h, w1.w, acc[7]);
    }
    const int lane = threadIdx.x & 31, wid = threadIdx.x >> 5;
#pragma unroll
    for (int j = 0; j < NEXP; j++)
#pragma unroll
        for (int o = 16; o > 0; o >>= 1)
            acc[j] += __shfl_down_sync(0xffffffffu, acc[j], o);
    __shared__ float red[8][NEXP];
    if (lane == 0) {
#pragma unroll
        for (int j = 0; j < NEXP; j++) red[wid][j] = acc[j];
    }
    __syncthreads();
    if (threadIdx.x == 0) {
        float l[NEXP];
#pragma unroll
        for (int j = 0; j < NEXP; j++) {
            l[j] = gb2[j];
#pragma unroll
            for (int w = 0; w < 8; w++) l[j] += red[w][j];
        }
        float mx = l[0];
#pragma unroll
        for (int j = 1; j < NEXP; j++) mx = fmaxf(mx, l[j]);
        float p[NEXP], s = 0.f;
#pragma unroll
        for (int j = 0; j < NEXP; j++) { p[j] = expf(l[j] - mx); s += p[j]; }
        float inv = 1.0f / s;
#pragma unroll
        for (int j = 0; j < NEXP; j++) p[j] *= inv;
        int i0 = 0;
#pragma unroll
        for (int j = 1; j < NEXP; j++) if (p[j] > p[i0]) i0 = j;
        int i1 = (i0 == 0) ? 1 : 0;
#pragma unroll
        for (int j = 0; j < NEXP; j++) if (j != i0 && p[j] > p[i1]) i1 = j;
        g_topk_idx[t * 2 + 0] = i0;  g_topk_w[t * 2 + 0] = p[i0];
        g_topk_idx[t * 2 + 1] = i1;  g_topk_w[t * 2 + 1] = p[i1];
    }
}

// ---------------- deterministic dispatch ----------------
__global__ void dispatch_count() {
    __shared__ int scnt[NEXP];
    if (threadIdx.x < NEXP) scnt[threadIdx.x] = 0;
    __syncthreads();
    int item = blockIdx.x * 256 + threadIdx.x;
    atomicAdd(&scnt[g_topk_idx[item]], 1);
    __syncthreads();
    if (threadIdx.x < NEXP) g_blockCnt[blockIdx.x * NEXP + threadIdx.x] = scnt[threadIdx.x];
}
__global__ void dispatch_scan() {
    int e = threadIdx.x;
    if (e < NEXP) {
        int off = 0;
        for (int b = 0; b < NBLK_DISP; b++) {
            g_blockOff[b * NEXP + e] = off;
            off += g_blockCnt[b * NEXP + e];
        }
        g_cnt[e] = off;
    }
    __syncthreads();
    if (threadIdx.x == 0) {
        int base = 0, mb = 0;
        for (int i = 0; i < NEXP; i++) {
            g_base[i] = base; base += g_cnt[i];
            g_mblkBase[i] = mb; mb += (g_cnt[i] + 127) >> 7;
        }
        g_mblkBase[NEXP] = mb;
    }
}
__global__ void dispatch_write() {
    __shared__ int se[256];
    const int i = threadIdx.x;
    const int item = blockIdx.x * 256 + i;
    const int e = g_topk_idx[item];
    se[i] = e;
    __syncthreads();
    int rank = 0;
    for (int j = 0; j < i; j++) rank += (se[j] == e);
    int pos = g_base[e] + g_blockOff[blockIdx.x * NEXP + e] + rank;
    g_list[pos]  = item >> 1;
    g_wlist[pos] = g_topk_w[item];
}

// ---------------- launch ----------------
extern "C" void kernel_launch(void* const* d_in, const int* in_sizes, int n_in,
                              void* d_out, int out_size)
{
    const float* x   = (const float*)d_in[0];
    const float* gw1 = (const float*)d_in[2];
    const float* gb1 = (const float*)d_in[3];
    const float* gw2 = (const float*)d_in[4];
    const float* gb2 = (const float*)d_in[5];
    const float* We1 = (const float*)d_in[6];
    const float* be1 = (const float*)d_in[7];
    const float* We2 = (const float*)d_in[8];
    const float* be2 = (const float*)d_in[9];
    const float* Ws1 = (const float*)d_in[10];
    const float* bs1 = (const float*)d_in[11];
    const float* Ws2 = (const float*)d_in[12];
    const float* bs2 = (const float*)d_in[13];
    float* out = (float*)d_out;

    float  *h1;
    __half *hs, *he, *xhi, *xlo, *Bg1h, *Bg1l, *Bs1h, *Bs2h, *Be1h, *Be2h;
    cudaGetSymbolAddress((void**)&h1,   g_h1);
    cudaGetSymbolAddress((void**)&hs,   g_hs);
    cudaGetSymbolAddress((void**)&he,   g_he);
    cudaGetSymbolAddress((void**)&xhi,  g_xhi);
    cudaGetSymbolAddress((void**)&xlo,  g_xlo);
    cudaGetSymbolAddress((void**)&Bg1h, g_Bg1h);
    cudaGetSymbolAddress((void**)&Bg1l, g_Bg1l);
    cudaGetSymbolAddress((void**)&Bs1h, g_Bs1h);
    cudaGetSymbolAddress((void**)&Bs2h, g_Bs2h);
    cudaGetSymbolAddress((void**)&Be1h, g_Be1h);
    cudaGetSymbolAddress((void**)&Be2h, g_Be2h);

    cudaFuncSetAttribute(gemm_gate,       cudaFuncAttributeMaxDynamicSharedMemorySize, SMG_BYTES);
    cudaFuncSetAttribute(gemm_f16<0,2,1>, cudaFuncAttributeMaxDynamicSharedMemorySize, SME_BYTES);
    cudaFuncSetAttribute(gemm_f16<0,0,0>, cudaFuncAttributeMaxDynamicSharedMemorySize, SME_BYTES);
    cudaFuncSetAttribute(gemm_f16<1,2,1>, cudaFuncAttributeMaxDynamicSharedMemorySize, SME_BYTES);
    cudaFuncSetAttribute(gemm_f16<2,0,2>, cudaFuncAttributeMaxDynamicSharedMemorySize, SME_BYTES);

    // conversions / transposes
    cvt_hilo<<<(T_TOK * DIMD / 4 + 255) / 256, 256>>>(x, xhi, xlo, T_TOK * DIMD / 4);
    dim3 t32(32, 8);
    transpose_cvt<true ><<<dim3(DIMH / 32, DIMD / 32, 1),    t32>>>(gw1, Bg1h, Bg1l, DIMD, DIMH);
    transpose_cvt<false><<<dim3(DIMH / 32, DIMD / 32, 1),    t32>>>(Ws1, Bs1h, nullptr, DIMD, DIMH);
    transpose_cvt<false><<<dim3(DIMD / 32, DIMH / 32, 1),    t32>>>(Ws2, Bs2h, nullptr, DIMH, DIMD);
    transpose_cvt<false><<<dim3(DIMH / 32, DIMD / 32, NEXP), t32>>>(We1, Be1h, nullptr, DIMD, DIMH);
    transpose_cvt<false><<<dim3(DIMD / 32, DIMH / 32, NEXP), t32>>>(We2, Be2h, nullptr, DIMH, DIMD);

    // 1) gate hidden (3-pass fp16, fp32 out): h1 = gelu_erf(x @ gw1 + gb1)
    gemm_gate<<<dim3(T_TOK / 128, DIMH / 64), 256, SMG_BYTES>>>(xhi, xlo, Bg1h, Bg1l, gb1, h1, DIMD);
    // 2) routing
    logits_topk<<<T_TOK, 256>>>(h1, gw2, gb2);
    dispatch_count<<<NBLK_DISP, 256>>>();
    dispatch_scan<<<1, 32>>>();
    dispatch_write<<<NBLK_DISP, 256>>>();
    // 3) shared expert
    gemm_f16<0,2,1><<<dim3(T_TOK / 128, DIMH / 128), 256, SME_BYTES>>>(xhi, Bs1h, bs1, hs,  DIMD, DIMH);
    gemm_f16<0,0,0><<<dim3(T_TOK / 128, DIMD / 128), 256, SME_BYTES>>>(hs,  Bs2h, bs2, out, DIMH, DIMD);
    // 4) routed experts
    gemm_f16<1,2,1><<<dim3(136, DIMH / 128), 256, SME_BYTES>>>(xhi, Be1h, be1, he,  DIMD, DIMH);
    gemm_f16<2,0,2><<<dim3(136, DIMD / 128), 256, SME_BYTES>>>(he,  Be2h, be2, out, DIMH, DIMD);
}

// round 4
// speedup vs baseline: 5.3147x; 1.4212x over previous
#include <cuda_runtime.h>
#include <cuda_fp16.h>
#include <cstdint>
#include <math.h>

// ---------------- problem constants ----------------
#define T_TOK 8192
#define DIMD  1024
#define DIMH  2048
#define NEXP  8
#define NITEM (T_TOK*2)
#define NBLK_DISP 64
#define MARGIN_TAU 1e-3f

// ---------------- scratch (device globals) ----------------
__device__ float  g_h1[(size_t)T_TOK * DIMH];           // gate hidden fp32; later reused as repair h buffer
__device__ __half g_hs[(size_t)T_TOK * DIMH];           // shared-expert hidden fp16
__device__ __half g_he[(size_t)NITEM * DIMH];           // routed hidden fp16 (compact)
__device__ float  g_ho[(size_t)NITEM * DIMD];           // routed out rows (weighted, compact)
__device__ __half g_xhi[(size_t)T_TOK * DIMD];
__device__ __half g_Bg1h[(size_t)DIMH * DIMD];          // gw1^T fp16
__device__ __half g_Bs1h[(size_t)DIMH * DIMD];
__device__ __half g_Bs2h[(size_t)DIMD * DIMH];
__device__ __half g_Be1h[(size_t)NEXP * DIMH * DIMD];
__device__ __half g_Be2h[(size_t)NEXP * DIMD * DIMH];
__device__ int    g_topk_idx[NITEM];
__device__ float  g_topk_w[NITEM];
__device__ int    g_list[NITEM];
__device__ float  g_wlist[NITEM];
__device__ int    g_slot[NITEM];                        // item -> compact slot
__device__ int    g_cnt[NEXP];
__device__ int    g_base[NEXP];
__device__ int    g_mblkBase[NEXP + 1];
__device__ int    g_blockCnt[NBLK_DISP * NEXP];
__device__ int    g_blockOff[NBLK_DISP * NEXP];
__device__ int    g_fixCnt;
__device__ int    g_fixList[T_TOK];

// ---------------- PTX helpers (baseline sm_80+ features only) ----------------
__device__ __forceinline__ uint32_t smem_u32(const void* p) {
    uint32_t a;
    asm("{ .reg .u64 t; cvta.to.shared.u64 t, %1; cvt.u32.u64 %0, t; }" : "=r"(a) : "l"(p));
    return a;
}
__device__ __forceinline__ void ldsm4(uint32_t& r0, uint32_t& r1, uint32_t& r2, uint32_t& r3, uint32_t a) {
    asm volatile("ldmatrix.sync.aligned.m8n8.x4.shared.b16 {%0,%1,%2,%3}, [%4];"
                 : "=r"(r0), "=r"(r1), "=r"(r2), "=r"(r3) : "r"(a));
}
__device__ __forceinline__ void mma16816(float* d, const uint32_t* a, const uint32_t* b) {
    asm volatile("mma.sync.aligned.m16n8k16.row.col.f32.f16.f16.f32 "
                 "{%0,%1,%2,%3},{%4,%5,%6,%7},{%8,%9},{%0,%1,%2,%3};"
                 : "+f"(d[0]), "+f"(d[1]), "+f"(d[2]), "+f"(d[3])
                 : "r"(a[0]), "r"(a[1]), "r"(a[2]), "r"(a[3]), "r"(b[0]), "r"(b[1]));
}
#define CP_ASYNC16(sa, ga) asm volatile("cp.async.cg.shared.global [%0], [%1], 16;" :: "r"(sa), "l"(ga))
#define CP_COMMIT()        asm volatile("cp.async.commit_group;" ::: "memory")
template<int N> __device__ __forceinline__ void cp_wait() {
    asm volatile("cp.async.wait_group %0;" :: "n"(N) : "memory");
}

// ---------------- activations ----------------
__device__ __forceinline__ float gelu_erf(float v) {
    return 0.5f * v * (1.0f + erff(v * 0.70710678118654752f));
}
__device__ __forceinline__ float gelu_tanh(float v) {
    float u = 0.7978845608028654f * (v + 0.044715f * v * v * v);
    float t = __expf(2.0f * u);
    float th = 1.0f - __fdividef(2.0f, t + 1.0f);
    return 0.5f * v * (1.0f + th);
}

// ---------------- conversions ----------------
__global__ void cvt_hi(const float* __restrict__ src, __half* __restrict__ hi, int n4) {
    int i = blockIdx.x * blockDim.x + threadIdx.x;
    if (i >= n4) return;
    float4 v = reinterpret_cast<const float4*>(src)[i];
    __half2* hp = reinterpret_cast<__half2*>(hi) + 2 * i;
    hp[0] = __halves2half2(__float2half_rn(v.x), __float2half_rn(v.y));
    hp[1] = __halves2half2(__float2half_rn(v.z), __float2half_rn(v.w));
}

// transpose [R,C] fp32 -> [C,R] fp16, batched z
__global__ void transpose_cvt(const float* __restrict__ src, __half* __restrict__ dst, int R, int C) {
    __shared__ float t[32][33];
    size_t zs = (size_t)blockIdx.z * R * C;
    int c0 = blockIdx.x * 32, r0 = blockIdx.y * 32;
    int x = threadIdx.x, y = threadIdx.y;
#pragma unroll
    for (int dy = 0; dy < 32; dy += 8)
        t[y + dy][x] = src[zs + (size_t)(r0 + y + dy) * C + c0 + x];
    __syncthreads();
#pragma unroll
    for (int dy = 0; dy < 32; dy += 8)
        dst[zs + (size_t)(c0 + y + dy) * R + r0 + x] = __float2half_rn(t[x][y + dy]);
}

__global__ void reset_fix() { if (threadIdx.x == 0) g_fixCnt = 0; }

// ---------------- fp16 tensor GEMM: CTA 128x128, BK=64, 3-stage cp.async ----------------
// MODE 0: dense A rows; 1: gather A rows via g_list (expert blocks); 2: dense compact A
// ACT 0: none, 1: gelu_erf, 2: gelu_tanh
// OUT 0: fp32 store; 1: fp16 store; 3: weighted fp32 store to compact row (base+m)
#define ROWPAD144 144
#define TILE_P (128 * ROWPAD144)      // 18432 B
#define STAGE_E (2 * TILE_P)          // A + B = 36864
#define SME_BYTES (3 * STAGE_E)       // 110592

template<int MODE, int ACT, int OUT>
__global__ __launch_bounds__(256, 2)
void gemm_f16(const __half* __restrict__ A, const __half* __restrict__ Bt,
              const float* __restrict__ bias, void* __restrict__ Cv,
              int K, int ldc)
{
    int e = 0, m0, base = 0, cnt = 0;
    const int Nfull = gridDim.y * 128;
    if (MODE == 0) {
        m0 = blockIdx.x * 128;
    } else {
        if ((int)blockIdx.x >= g_mblkBase[NEXP]) return;
#pragma unroll
        for (int i = 1; i < NEXP; i++) if ((int)blockIdx.x >= g_mblkBase[i]) e = i;
        m0 = ((int)blockIdx.x - g_mblkBase[e]) * 128;
        base = g_base[e]; cnt = g_cnt[e];
        Bt   += (size_t)e * Nfull * K;
        bias += (size_t)e * Nfull;
    }
    const int n0 = blockIdx.y * 128;

    extern __shared__ char smem[];
    const uint32_t sbase = smem_u32(smem);
    const int tid = threadIdx.x, lane = tid & 31, wid = tid >> 5;

    const int lrow = tid >> 3;
    const uint32_t dstOff = (uint32_t)(lrow * ROWPAD144 + (tid & 7) * 16);
    const __half* aptr[4];
#pragma unroll
    for (int i = 0; i < 4; i++) {
        int m = m0 + lrow + 32 * i;
        if (MODE == 0)      aptr[i] = A + (size_t)m * K;
        else if (MODE == 1) { int mm = (m < cnt) ? m : 0; aptr[i] = A + (size_t)g_list[base + mm] * K; }
        else                { int mm = (m < cnt) ? m : 0; aptr[i] = A + (size_t)(base + mm) * K; }
        aptr[i] += (tid & 7) * 8;
    }
    const __half* bptr[4];
#pragma unroll
    for (int i = 0; i < 4; i++)
        bptr[i] = Bt + (size_t)(n0 + lrow + 32 * i) * K + (tid & 7) * 8;

    const int S = K >> 6;
    auto issue = [&](int s) {
        uint32_t st = sbase + (uint32_t)((s % 3) * STAGE_E);
#pragma unroll
        for (int i = 0; i < 4; i++) CP_ASYNC16(st + dstOff + (uint32_t)(32 * i * ROWPAD144), (const void*)(aptr[i] + s * 64));
#pragma unroll
        for (int i = 0; i < 4; i++) CP_ASYNC16(st + TILE_P + dstOff + (uint32_t)(32 * i * ROWPAD144), (const void*)(bptr[i] + s * 64));
        CP_COMMIT();
    };
    issue(0);
    if (S > 1) issue(1);

    const int wm0 = (wid >> 1) * 32;
    const int wn0 = (wid & 1) * 64;
    const int arow_l = (lane & 7) + ((lane >> 3) & 1) * 8;
    const int acol_l = (lane >> 4) * 8;
    const int brow_l = (lane >> 4) * 8 + (lane & 7);
    const int bcol_l = ((lane >> 3) & 1) * 8;

    float acc[2][8][4];
#pragma unroll
    for (int i = 0; i < 2; i++)
#pragma unroll
        for (int j = 0; j < 8; j++)
#pragma unroll
            for (int q = 0; q < 4; q++) acc[i][j][q] = 0.f;

    for (int s = 0; s < S; s++) {
        if (s + 2 < S) { issue(s + 2); cp_wait<2>(); }
        else if (s + 1 < S) cp_wait<1>();
        else cp_wait<0>();
        __syncthreads();

        const uint32_t st = sbase + (uint32_t)((s % 3) * STAGE_E);
        const uint32_t sA = st, sB = st + TILE_P;
#pragma unroll
        for (int ks = 0; ks < 4; ks++) {
            const int k0 = ks * 16;
            uint32_t a[2][4], b[4][4];
#pragma unroll
            for (int mf = 0; mf < 2; mf++)
                ldsm4(a[mf][0], a[mf][1], a[mf][2], a[mf][3],
                      sA + (uint32_t)((wm0 + mf * 16 + arow_l) * ROWPAD144 + (k0 + acol_l) * 2));
#pragma unroll
            for (int p = 0; p < 4; p++)
                ldsm4(b[p][0], b[p][1], b[p][2], b[p][3],
                      sB + (uint32_t)((wn0 + p * 16 + brow_l) * ROWPAD144 + (k0 + bcol_l) * 2));
#pragma unroll
            for (int mf = 0; mf < 2; mf++)
#pragma unroll
                for (int nf = 0; nf < 8; nf++)
                    mma16816(acc[mf][nf], a[mf], &b[nf >> 1][(nf & 1) * 2]);
        }
        __syncthreads();
    }

    // ---- epilogue ----
    const int tr = lane >> 2, tc = (lane & 3) * 2;
#pragma unroll
    for (int mf = 0; mf < 2; mf++) {
#pragma unroll
        for (int half_ = 0; half_ < 2; half_++) {
            const int m = m0 + wm0 + mf * 16 + tr + half_ * 8;
            bool ok = (MODE == 0) || (m < cnt);
            if (!ok) continue;
            int orow = m; float wgt = 1.f;
            if (MODE == 1) orow = base + m;
            if (MODE == 2) {
                if (OUT == 3) { orow = base + m; wgt = g_wlist[base + m]; }
                else          { orow = g_list[base + m]; wgt = g_wlist[base + m]; }
            }
#pragma unroll
            for (int nf = 0; nf < 8; nf++) {
                const int c = n0 + wn0 + nf * 8 + tc;
                float v0 = acc[mf][nf][half_ * 2 + 0] + bias[c];
                float v1 = acc[mf][nf][half_ * 2 + 1] + bias[c + 1];
                if (ACT == 1) { v0 = gelu_erf(v0);  v1 = gelu_erf(v1); }
                if (ACT == 2) { v0 = gelu_tanh(v0); v1 = gelu_tanh(v1); }
                if (OUT == 0) {
                    float2 w2; w2.x = v0; w2.y = v1;
                    *reinterpret_cast<float2*>((float*)Cv + (size_t)orow * ldc + c) = w2;
                } else if (OUT == 1) {
                    *reinterpret_cast<__half2*>((__half*)Cv + (size_t)orow * ldc + c) =
                        __halves2half2(__float2half_rn(v0), __float2half_rn(v1));
                } else {
                    float2 w2; w2.x = wgt * v0; w2.y = wgt * v1;
                    *reinterpret_cast<float2*>((float*)Cv + (size_t)orow * ldc + c) = w2;
                }
            }
        }
    }
}

// ---------------- fp32 repair SGEMM: gathered rows (g_fixList), gelu_erf, compact out ----------------
__global__ __launch_bounds__(256, 2)
void sgemm_fix(const float* __restrict__ A, const float* __restrict__ B,
               const float* __restrict__ bias, float* __restrict__ C)
{
    const int cnt = g_fixCnt;
    const int m0 = blockIdx.x * 128;
    if (m0 >= cnt) return;
    const int n0 = blockIdx.y * 128;
    const int K = DIMD, N = DIMH;

    __shared__ float As[8][128];
    __shared__ float Bs[8][128];
    const int tid = threadIdx.x;
    const int aRow = tid >> 1, aCol = (tid & 1) * 4;
    const int bRow = tid >> 5, bCol = (tid & 31) * 4;

    int mA = m0 + aRow;
    int mm = (mA < cnt) ? mA : 0;
    const float* Arow = A + (size_t)g_fixList[mm] * K;
    const float* Bp = B + (size_t)bRow * N + n0 + bCol;

    const int ty = tid >> 4, tx = tid & 15;
    float acc[8][8];
#pragma unroll
    for (int i = 0; i < 8; i++)
#pragma unroll
        for (int j = 0; j < 8; j++) acc[i][j] = 0.f;

    for (int k0 = 0; k0 < K; k0 += 8) {
        float4 av = *reinterpret_cast<const float4*>(Arow + k0 + aCol);
        As[aCol + 0][aRow] = av.x; As[aCol + 1][aRow] = av.y;
        As[aCol + 2][aRow] = av.z; As[aCol + 3][aRow] = av.w;
        *reinterpret_cast<float4*>(&Bs[bRow][bCol]) = *reinterpret_cast<const float4*>(Bp + (size_t)k0 * N);
        __syncthreads();
#pragma unroll
        for (int kk = 0; kk < 8; kk++) {
            float4 a0 = *reinterpret_cast<const float4*>(&As[kk][ty * 8]);
            float4 a1 = *reinterpret_cast<const float4*>(&As[kk][ty * 8 + 4]);
            float4 b0 = *reinterpret_cast<const float4*>(&Bs[kk][tx * 8]);
            float4 b1 = *reinterpret_cast<const float4*>(&Bs[kk][tx * 8 + 4]);
            float a[8] = {a0.x, a0.y, a0.z, a0.w, a1.x, a1.y, a1.z, a1.w};
            float b[8] = {b0.x, b0.y, b0.z, b0.w, b1.x, b1.y, b1.z, b1.w};
#pragma unroll
            for (int i = 0; i < 8; i++)
#pragma unroll
                for (int j = 0; j < 8; j++)
                    acc[i][j] = fmaf(a[i], b[j], acc[i][j]);
        }
        __syncthreads();
    }
    const int cRow0 = m0 + ty * 8, cCol0 = n0 + tx * 8;
#pragma unroll
    for (int i = 0; i < 8; i++) {
        int m = cRow0 + i;
        if (m >= cnt) continue;
#pragma unroll
        for (int j = 0; j < 8; j++)
            C[(size_t)m * N + cCol0 + j] = gelu_erf(acc[i][j] + bias[cCol0 + j]);
    }
}

// ---------------- logits + softmax + top-2 + margin flag ----------------
__device__ __forceinline__ void logits_core(const float* __restrict__ hrow,
                                            const float* __restrict__ gw2,
                                            const float* __restrict__ gb2,
                                            float (&red)[8][NEXP],
                                            int t, bool flag_enable)
{
    float acc[NEXP];
#pragma unroll
    for (int j = 0; j < NEXP; j++) acc[j] = 0.f;
    for (int i = threadIdx.x; i < DIMH; i += 256) {
        float h = hrow[i];
        float4 w0 = *reinterpret_cast<const float4*>(gw2 + (size_t)i * NEXP);
        float4 w1 = *reinterpret_cast<const float4*>(gw2 + (size_t)i * NEXP + 4);
        acc[0] = fmaf(h, w0.x, acc[0]); acc[1] = fmaf(h, w0.y, acc[1]);
        acc[2] = fmaf(h, w0.z, acc[2]); acc[3] = fmaf(h, w0.w, acc[3]);
        acc[4] = fmaf(h, w1.x, acc[4]); acc[5] = fmaf(h, w1.y, acc[5]);
        acc[6] = fmaf(h, w1.z, acc[6]); acc[7] = fmaf(h, w1.w, acc[7]);
    }
    const int lane = threadIdx.x & 31, wid = threadIdx.x >> 5;
#pragma unroll
    for (int j = 0; j < NEXP; j++)
#pragma unroll
        for (int o = 16; o > 0; o >>= 1)
            acc[j] += __shfl_down_sync(0xffffffffu, acc[j], o);
    if (lane == 0) {
#pragma unroll
        for (int j = 0; j < NEXP; j++) red[wid][j] = acc[j];
    }
    __syncthreads();
    if (threadIdx.x == 0) {
        float l[NEXP];
#pragma unroll
        for (int j = 0; j < NEXP; j++) {
            l[j] = gb2[j];
#pragma unroll
            for (int w = 0; w < 8; w++) l[j] += red[w][j];
        }
        float mx = l[0];
#pragma unroll
        for (int j = 1; j < NEXP; j++) mx = fmaxf(mx, l[j]);
        float p[NEXP], s = 0.f;
#pragma unroll
        for (int j = 0; j < NEXP; j++) { p[j] = expf(l[j] - mx); s += p[j]; }
        float inv = 1.0f / s;
#pragma unroll
        for (int j = 0; j < NEXP; j++) p[j] *= inv;
        int i0 = 0;
#pragma unroll
        for (int j = 1; j < NEXP; j++) if (p[j] > p[i0]) i0 = j;
        int i1 = (i0 == 0) ? 1 : 0;
#pragma unroll
        for (int j = 0; j < NEXP; j++) if (j != i0 && p[j] > p[i1]) i1 = j;
        g_topk_idx[t * 2 + 0] = i0;  g_topk_w[t * 2 + 0] = p[i0];
        g_topk_idx[t * 2 + 1] = i1;  g_topk_w[t * 2 + 1] = p[i1];
        if (flag_enable) {
            float p2 = -1.f;
#pragma unroll
            for (int j = 0; j < NEXP; j++)
                if (j != i0 && j != i1 && p[j] > p2) p2 = p[j];
            if (p[i1] - p2 < MARGIN_TAU) {
                int ix = atomicAdd(&g_fixCnt, 1);
                g_fixList[ix] = t;
            }
        }
    }
    __syncthreads();
}

__global__ void logits_topk(const float* __restrict__ h1,
                            const float* __restrict__ gw2,
                            const float* __restrict__ gb2)
{
    __shared__ float red[8][NEXP];
    const int t = blockIdx.x;
    logits_core(h1 + (size_t)t * DIMH, gw2, gb2, red, t, true);
}

__global__ void repair_logits(const float* __restrict__ hf,
                              const float* __restrict__ gw2,
                              const float* __restrict__ gb2)
{
    __shared__ float red[8][NEXP];
    for (int r = blockIdx.x; r < g_fixCnt; r += gridDim.x) {
        int t = g_fixList[r];
        logits_core(hf + (size_t)r * DIMH, gw2, gb2, red, t, false);
    }
}

// ---------------- deterministic dispatch ----------------
__global__ void dispatch_count() {
    __shared__ int scnt[NEXP];
    if (threadIdx.x < NEXP) scnt[threadIdx.x] = 0;
    __syncthreads();
    int item = blockIdx.x * 256 + threadIdx.x;
    atomicAdd(&scnt[g_topk_idx[item]], 1);
    __syncthreads();
    if (threadIdx.x < NEXP) g_blockCnt[blockIdx.x * NEXP + threadIdx.x] = scnt[threadIdx.x];
}
__global__ void dispatch_scan() {
    int e = threadIdx.x;
    if (e < NEXP) {
        int off = 0;
        for (int b = 0; b < NBLK_DISP; b++) {
            g_blockOff[b * NEXP + e] = off;
            off += g_blockCnt[b * NEXP + e];
        }
        g_cnt[e] = off;
    }
    __syncthreads();
    if (threadIdx.x == 0) {
        int base = 0, mb = 0;
        for (int i = 0; i < NEXP; i++) {
            g_base[i] = base; base += g_cnt[i];
            g_mblkBase[i] = mb; mb += (g_cnt[i] + 127) >> 7;
        }
        g_mblkBase[NEXP] = mb;
    }
}
__global__ void dispatch_write() {
    __shared__ int se[256];
    const int i = threadIdx.x;
    const int item = blockIdx.x * 256 + i;
    const int e = g_topk_idx[item];
    se[i] = e;
    __syncthreads();
    int rank = 0;
    for (int j = 0; j < i; j++) rank += (se[j] == e);
    int pos = g_base[e] + g_blockOff[blockIdx.x * NEXP + e] + rank;
    g_list[pos]  = item >> 1;
    g_wlist[pos] = g_topk_w[item];
    g_slot[item] = pos;
}

// ---------------- combine: out[t] += ho[slot0] + ho[slot1] ----------------
__global__ void combine(const float* __restrict__ ho, float* __restrict__ out) {
    const int t = blockIdx.x;
    const int c = threadIdx.x * 4;
    const int s0 = g_slot[2 * t], s1 = g_slot[2 * t + 1];
    float4 o = *reinterpret_cast<float4*>(out + (size_t)t * DIMD + c);
    float4 a = *reinterpret_cast<const float4*>(ho + (size_t)s0 * DIMD + c);
    float4 b = *reinterpret_cast<const float4*>(ho + (size_t)s1 * DIMD + c);
    o.x += a.x + b.x; o.y += a.y + b.y; o.z += a.z + b.z; o.w += a.w + b.w;
    *reinterpret_cast<float4*>(out + (size_t)t * DIMD + c) = o;
}

// ---------------- launch ----------------
extern "C" void kernel_launch(void* const* d_in, const int* in_sizes, int n_in,
                              void* d_out, int out_size)
{
    const float* x   = (const float*)d_in[0];
    const float* gw1 = (const float*)d_in[2];
    const float* gb1 = (const float*)d_in[3];
    const float* gw2 = (const float*)d_in[4];
    const float* gb2 = (const float*)d_in[5];
    const float* We1 = (const float*)d_in[6];
    const float* be1 = (const float*)d_in[7];
    const float* We2 = (const float*)d_in[8];
    const float* be2 = (const float*)d_in[9];
    const float* Ws1 = (const float*)d_in[10];
    const float* bs1 = (const float*)d_in[11];
    const float* Ws2 = (const float*)d_in[12];
    const float* bs2 = (const float*)d_in[13];
    float* out = (float*)d_out;

    float  *h1, *ho;
    __half *hs, *he, *xhi, *Bg1h, *Bs1h, *Bs2h, *Be1h, *Be2h;
    cudaGetSymbolAddress((void**)&h1,   g_h1);
    cudaGetSymbolAddress((void**)&ho,   g_ho);
    cudaGetSymbolAddress((void**)&hs,   g_hs);
    cudaGetSymbolAddress((void**)&he,   g_he);
    cudaGetSymbolAddress((void**)&xhi,  g_xhi);
    cudaGetSymbolAddress((void**)&Bg1h, g_Bg1h);
    cudaGetSymbolAddress((void**)&Bs1h, g_Bs1h);
    cudaGetSymbolAddress((void**)&Bs2h, g_Bs2h);
    cudaGetSymbolAddress((void**)&Be1h, g_Be1h);
    cudaGetSymbolAddress((void**)&Be2h, g_Be2h);

    cudaFuncSetAttribute(gemm_f16<0,1,0>, cudaFuncAttributeMaxDynamicSharedMemorySize, SME_BYTES);
    cudaFuncSetAttribute(gemm_f16<0,2,1>, cudaFuncAttributeMaxDynamicSharedMemorySize, SME_BYTES);
    cudaFuncSetAttribute(gemm_f16<0,0,0>, cudaFuncAttributeMaxDynamicSharedMemorySize, SME_BYTES);
    cudaFuncSetAttribute(gemm_f16<1,2,1>, cudaFuncAttributeMaxDynamicSharedMemorySize, SME_BYTES);
    cudaFuncSetAttribute(gemm_f16<2,0,3>, cudaFuncAttributeMaxDynamicSharedMemorySize, SME_BYTES);

    // prep
    cvt_hi<<<(T_TOK * DIMD / 4 + 255) / 256, 256>>>(x, xhi, T_TOK * DIMD / 4);
    dim3 t32(32, 8);
    transpose_cvt<<<dim3(DIMH / 32, DIMD / 32, 1),    t32>>>(gw1, Bg1h, DIMD, DIMH);
    transpose_cvt<<<dim3(DIMH / 32, DIMD / 32, 1),    t32>>>(Ws1, Bs1h, DIMD, DIMH);
    transpose_cvt<<<dim3(DIMD / 32, DIMH / 32, 1),    t32>>>(Ws2, Bs2h, DIMH, DIMD);
    transpose_cvt<<<dim3(DIMH / 32, DIMD / 32, NEXP), t32>>>(We1, Be1h, DIMD, DIMH);
    transpose_cvt<<<dim3(DIMD / 32, DIMH / 32, NEXP), t32>>>(We2, Be2h, DIMH, DIMD);
    reset_fix<<<1, 32>>>();

    // 1) gate hidden single-pass fp16, fp32 out
    gemm_f16<0,1,0><<<dim3(T_TOK / 128, DIMH / 128), 256, SME_BYTES>>>(xhi, Bg1h, gb1, h1, DIMD, DIMH);
    // 2) routing + margin flags
    logits_topk<<<T_TOK, 256>>>(h1, gw2, gb2);
    // 3) fp32 repair of low-margin tokens (reuses h1 buffer compactly)
    sgemm_fix<<<dim3(T_TOK / 128, DIMH / 128), 256>>>(x, gw1, gb1, h1);
    repair_logits<<<512, 256>>>(h1, gw2, gb2);
    // 4) dispatch
    dispatch_count<<<NBLK_DISP, 256>>>();
    dispatch_scan<<<1, 32>>>();
    dispatch_write<<<NBLK_DISP, 256>>>();
    // 5) shared expert
    gemm_f16<0,2,1><<<dim3(T_TOK / 128, DIMH / 128), 256, SME_BYTES>>>(xhi, Bs1h, bs1, hs,  DIMD, DIMH);
    gemm_f16<0,0,0><<<dim3(T_TOK / 128, DIMD / 128), 256, SME_BYTES>>>(hs,  Bs2h, bs2, out, DIMH, DIMD);
    // 6) routed experts: gathered gemm1 -> he (fp16), gemm2 -> ho (weighted, compact)
    gemm_f16<1,2,1><<<dim3(136, DIMH / 128), 256, SME_BYTES>>>(xhi, Be1h, be1, he, DIMD, DIMH);
    gemm_f16<2,0,3><<<dim3(136, DIMD / 128), 256, SME_BYTES>>>(he,  Be2h, be2, ho, DIMH, DIMD);
    // 7) combine routed into out
    combine<<<T_TOK, 256>>>(ho, out);
}

// round 5
// speedup vs baseline: 5.3560x; 1.0078x over previous
#include <cuda_runtime.h>
#include <cuda_fp16.h>
#include <cstdint>
#include <math.h>

// ---------------- problem constants ----------------
#define T_TOK 8192
#define DIMD  1024
#define DIMH  2048
#define NEXP  8
#define NITEM (T_TOK*2)
#define NBLK_DISP 64
#define MARGIN_TAU 1e-3f

// ---------------- scratch (device globals) ----------------
__device__ float  g_h1[(size_t)T_TOK * DIMH];           // gate hidden fp32; later reused as repair h buffer
__device__ __half g_hs[(size_t)T_TOK * DIMH];           // shared-expert hidden fp16
__device__ __half g_he[(size_t)NITEM * DIMH];           // routed hidden fp16 (compact)
__device__ float  g_ho[(size_t)NITEM * DIMD];           // routed out rows (weighted, compact)
__device__ __half g_xhi[(size_t)T_TOK * DIMD];
__device__ __half g_Bg1h[(size_t)DIMH * DIMD];          // gw1^T fp16
__device__ __half g_Bs1h[(size_t)DIMH * DIMD];
__device__ __half g_Bs2h[(size_t)DIMD * DIMH];
__device__ __half g_Be1h[(size_t)NEXP * DIMH * DIMD];
__device__ __half g_Be2h[(size_t)NEXP * DIMD * DIMH];
__device__ int    g_topk_idx[NITEM];
__device__ float  g_topk_w[NITEM];
__device__ int    g_list[NITEM];
__device__ float  g_wlist[NITEM];
__device__ int    g_slot[NITEM];                        // item -> compact slot
__device__ int    g_cnt[NEXP];
__device__ int    g_base[NEXP];
__device__ int    g_mblkBase[NEXP + 1];
__device__ int    g_blockCnt[NBLK_DISP * NEXP];
__device__ int    g_blockOff[NBLK_DISP * NEXP];
__device__ int    g_fixCnt;
__device__ int    g_fixList[T_TOK];

// ---------------- PTX helpers (baseline sm_80+ features only) ----------------
__device__ __forceinline__ uint32_t smem_u32(const void* p) {
    uint32_t a;
    asm("{ .reg .u64 t; cvta.to.shared.u64 t, %1; cvt.u32.u64 %0, t; }" : "=r"(a) : "l"(p));
    return a;
}
__device__ __forceinline__ void ldsm4(uint32_t& r0, uint32_t& r1, uint32_t& r2, uint32_t& r3, uint32_t a) {
    asm volatile("ldmatrix.sync.aligned.m8n8.x4.shared.b16 {%0,%1,%2,%3}, [%4];"
                 : "=r"(r0), "=r"(r1), "=r"(r2), "=r"(r3) : "r"(a));
}
__device__ __forceinline__ void mma16816(float* d, const uint32_t* a, const uint32_t* b) {
    asm volatile("mma.sync.aligned.m16n8k16.row.col.f32.f16.f16.f32 "
                 "{%0,%1,%2,%3},{%4,%5,%6,%7},{%8,%9},{%0,%1,%2,%3};"
                 : "+f"(d[0]), "+f"(d[1]), "+f"(d[2]), "+f"(d[3])
                 : "r"(a[0]), "r"(a[1]), "r"(a[2]), "r"(a[3]), "r"(b[0]), "r"(b[1]));
}
#define CP_ASYNC16(sa, ga) asm volatile("cp.async.cg.shared.global [%0], [%1], 16;" :: "r"(sa), "l"(ga))
#define CP_COMMIT()        asm volatile("cp.async.commit_group;" ::: "memory")
template<int N> __device__ __forceinline__ void cp_wait() {
    asm volatile("cp.async.wait_group %0;" :: "n"(N) : "memory");
}

// ---------------- activations ----------------
__device__ __forceinline__ float gelu_erf(float v) {
    return 0.5f * v * (1.0f + erff(v * 0.70710678118654752f));
}
__device__ __forceinline__ float gelu_tanh(float v) {
    float u = 0.7978845608028654f * (v + 0.044715f * v * v * v);
    float t = __expf(2.0f * u);
    float th = 1.0f - __fdividef(2.0f, t + 1.0f);
    return 0.5f * v * (1.0f + th);
}

// ---------------- conversions ----------------
__global__ void cvt_hi(const float* __restrict__ src, __half* __restrict__ hi, int n4) {
    int i = blockIdx.x * blockDim.x + threadIdx.x;
    if (i == 0) g_fixCnt = 0;                           // fused reset
    if (i >= n4) return;
    float4 v = reinterpret_cast<const float4*>(src)[i];
    __half2* hp = reinterpret_cast<__half2*>(hi) + 2 * i;
    hp[0] = __halves2half2(__float2half_rn(v.x), __float2half_rn(v.y));
    hp[1] = __halves2half2(__float2half_rn(v.z), __float2half_rn(v.w));
}

// transpose [R,C] fp32 -> [C,R] fp16, batched z
__global__ void transpose_cvt(const float* __restrict__ src, __half* __restrict__ dst, int R, int C) {
    __shared__ float t[32][33];
    size_t zs = (size_t)blockIdx.z * R * C;
    int c0 = blockIdx.x * 32, r0 = blockIdx.y * 32;
    int x = threadIdx.x, y = threadIdx.y;
#pragma unroll
    for (int dy = 0; dy < 32; dy += 8)
        t[y + dy][x] = src[zs + (size_t)(r0 + y + dy) * C + c0 + x];
    __syncthreads();
#pragma unroll
    for (int dy = 0; dy < 32; dy += 8)
        dst[zs + (size_t)(c0 + y + dy) * R + r0 + x] = __float2half_rn(t[x][y + dy]);
}

// ---------------- fp16 tensor GEMM: CTA 128x128, BK=64, 3-stage cp.async ----------------
// MODE 0: dense A rows; 1: gather A rows via g_list (expert blocks); 2: dense compact A
// ACT 0: none, 1: gelu_erf, 2: gelu_tanh
// OUT 0: fp32 store; 1: fp16 store; 3: weighted fp32 store to compact row (base+m)
#define ROWPAD144 144
#define TILE_P (128 * ROWPAD144)      // 18432 B
#define STAGE_E (2 * TILE_P)          // A + B = 36864
#define SME_BYTES (3 * STAGE_E)       // 110592

template<int MODE, int ACT, int OUT>
__global__ __launch_bounds__(256, 2)
void gemm_f16(const __half* __restrict__ A, const __half* __restrict__ Bt,
              const float* __restrict__ bias, void* __restrict__ Cv,
              int K, int ldc)
{
    int e = 0, m0, base = 0, cnt = 0;
    const int Nfull = gridDim.y * 128;
    if (MODE == 0) {
        m0 = blockIdx.x * 128;
    } else {
        if ((int)blockIdx.x >= g_mblkBase[NEXP]) return;
#pragma unroll
        for (int i = 1; i < NEXP; i++) if ((int)blockIdx.x >= g_mblkBase[i]) e = i;
        m0 = ((int)blockIdx.x - g_mblkBase[e]) * 128;
        base = g_base[e]; cnt = g_cnt[e];
        Bt   += (size_t)e * Nfull * K;
        bias += (size_t)e * Nfull;
    }
    const int n0 = blockIdx.y * 128;

    extern __shared__ char smem[];
    const uint32_t sbase = smem_u32(smem);
    const int tid = threadIdx.x, lane = tid & 31, wid = tid >> 5;

    const int lrow = tid >> 3;
    const uint32_t dstOff = (uint32_t)(lrow * ROWPAD144 + (tid & 7) * 16);
    const __half* aptr[4];
#pragma unroll
    for (int i = 0; i < 4; i++) {
        int m = m0 + lrow + 32 * i;
        if (MODE == 0)      aptr[i] = A + (size_t)m * K;
        else if (MODE == 1) { int mm = (m < cnt) ? m : 0; aptr[i] = A + (size_t)g_list[base + mm] * K; }
        else                { int mm = (m < cnt) ? m : 0; aptr[i] = A + (size_t)(base + mm) * K; }
        aptr[i] += (tid & 7) * 8;
    }
    const __half* bptr[4];
#pragma unroll
    for (int i = 0; i < 4; i++)
        bptr[i] = Bt + (size_t)(n0 + lrow + 32 * i) * K + (tid & 7) * 8;

    const int S = K >> 6;
    auto issue = [&](int s) {
        uint32_t st = sbase + (uint32_t)((s % 3) * STAGE_E);
#pragma unroll
        for (int i = 0; i < 4; i++) CP_ASYNC16(st + dstOff + (uint32_t)(32 * i * ROWPAD144), (const void*)(aptr[i] + s * 64));
#pragma unroll
        for (int i = 0; i < 4; i++) CP_ASYNC16(st + TILE_P + dstOff + (uint32_t)(32 * i * ROWPAD144), (const void*)(bptr[i] + s * 64));
        CP_COMMIT();
    };
    issue(0);
    if (S > 1) issue(1);

    const int wm0 = (wid >> 1) * 32;
    const int wn0 = (wid & 1) * 64;
    const int arow_l = (lane & 7) + ((lane >> 3) & 1) * 8;
    const int acol_l = (lane >> 4) * 8;
    const int brow_l = (lane >> 4) * 8 + (lane & 7);
    const int bcol_l = ((lane >> 3) & 1) * 8;

    float acc[2][8][4];
#pragma unroll
    for (int i = 0; i < 2; i++)
#pragma unroll
        for (int j = 0; j < 8; j++)
#pragma unroll
            for (int q = 0; q < 4; q++) acc[i][j][q] = 0.f;

    // single-barrier mainloop: wait -> sync -> prefetch(s+2) -> compute(s)
    // safe: slot((s+2)%3) == slot((s-1)%3); every warp past this barrier has
    // finished compute(s-1), so the overwrite cannot race a reader.
    for (int s = 0; s < S; s++) {
        if (s + 1 < S) cp_wait<1>(); else cp_wait<0>();
        __syncthreads();
        if (s + 2 < S) issue(s + 2);

        const uint32_t st = sbase + (uint32_t)((s % 3) * STAGE_E);
        const uint32_t sA = st, sB = st + TILE_P;
#pragma unroll
        for (int ks = 0; ks < 4; ks++) {
            const int k0 = ks * 16;
            uint32_t a[2][4], b[4][4];
#pragma unroll
            for (int mf = 0; mf < 2; mf++)
                ldsm4(a[mf][0], a[mf][1], a[mf][2], a[mf][3],
                      sA + (uint32_t)((wm0 + mf * 16 + arow_l) * ROWPAD144 + (k0 + acol_l) * 2));
#pragma unroll
            for (int p = 0; p < 4; p++)
                ldsm4(b[p][0], b[p][1], b[p][2], b[p][3],
                      sB + (uint32_t)((wn0 + p * 16 + brow_l) * ROWPAD144 + (k0 + bcol_l) * 2));
#pragma unroll
            for (int mf = 0; mf < 2; mf++)
#pragma unroll
                for (int nf = 0; nf < 8; nf++)
                    mma16816(acc[mf][nf], a[mf], &b[nf >> 1][(nf & 1) * 2]);
        }
    }

    // ---- epilogue ----
    const int tr = lane >> 2, tc = (lane & 3) * 2;
#pragma unroll
    for (int mf = 0; mf < 2; mf++) {
#pragma unroll
        for (int half_ = 0; half_ < 2; half_++) {
            const int m = m0 + wm0 + mf * 16 + tr + half_ * 8;
            bool ok = (MODE == 0) || (m < cnt);
            if (!ok) continue;
            int orow = m; float wgt = 1.f;
            if (MODE == 1) orow = base + m;
            if (MODE == 2) {
                if (OUT == 3) { orow = base + m; wgt = g_wlist[base + m]; }
                else          { orow = g_list[base + m]; wgt = g_wlist[base + m]; }
            }
#pragma unroll
            for (int nf = 0; nf < 8; nf++) {
                const int c = n0 + wn0 + nf * 8 + tc;
                float v0 = acc[mf][nf][half_ * 2 + 0] + bias[c];
                float v1 = acc[mf][nf][half_ * 2 + 1] + bias[c + 1];
                if (ACT == 1) { v0 = gelu_erf(v0);  v1 = gelu_erf(v1); }
                if (ACT == 2) { v0 = gelu_tanh(v0); v1 = gelu_tanh(v1); }
                if (OUT == 0) {
                    float2 w2; w2.x = v0; w2.y = v1;
                    *reinterpret_cast<float2*>((float*)Cv + (size_t)orow * ldc + c) = w2;
                } else if (OUT == 1) {
                    *reinterpret_cast<__half2*>((__half*)Cv + (size_t)orow * ldc + c) =
                        __halves2half2(__float2half_rn(v0), __float2half_rn(v1));
                } else {
                    float2 w2; w2.x = wgt * v0; w2.y = wgt * v1;
                    *reinterpret_cast<float2*>((float*)Cv + (size_t)orow * ldc + c) = w2;
                }
            }
        }
    }
}

// ---------------- fp32 repair SGEMM: gathered rows (g_fixList), gelu_erf, compact out ----------------
__global__ __launch_bounds__(256, 2)
void sgemm_fix(const float* __restrict__ A, const float* __restrict__ B,
               const float* __restrict__ bias, float* __restrict__ C)
{
    const int cnt = g_fixCnt;
    const int m0 = blockIdx.x * 128;
    if (m0 >= cnt) return;
    const int n0 = blockIdx.y * 128;
    const int K = DIMD, N = DIMH;

    __shared__ float As[8][128];
    __shared__ float Bs[8][128];
    const int tid = threadIdx.x;
    const int aRow = tid >> 1, aCol = (tid & 1) * 4;
    const int bRow = tid >> 5, bCol = (tid & 31) * 4;

    int mA = m0 + aRow;
    int mm = (mA < cnt) ? mA : 0;
    const float* Arow = A + (size_t)g_fixList[mm] * K;
    const float* Bp = B + (size_t)bRow * N + n0 + bCol;

    const int ty = tid >> 4, tx = tid & 15;
    float acc[8][8];
#pragma unroll
    for (int i = 0; i < 8; i++)
#pragma unroll
        for (int j = 0; j < 8; j++) acc[i][j] = 0.f;

    for (int k0 = 0; k0 < K; k0 += 8) {
        float4 av = *reinterpret_cast<const float4*>(Arow + k0 + aCol);
        As[aCol + 0][aRow] = av.x; As[aCol + 1][aRow] = av.y;
        As[aCol + 2][aRow] = av.z; As[aCol + 3][aRow] = av.w;
        *reinterpret_cast<float4*>(&Bs[bRow][bCol]) = *reinterpret_cast<const float4*>(Bp + (size_t)k0 * N);
        __syncthreads();
#pragma unroll
        for (int kk = 0; kk < 8; kk++) {
            float4 a0 = *reinterpret_cast<const float4*>(&As[kk][ty * 8]);
            float4 a1 = *reinterpret_cast<const float4*>(&As[kk][ty * 8 + 4]);
            float4 b0 = *reinterpret_cast<const float4*>(&Bs[kk][tx * 8]);
            float4 b1 = *reinterpret_cast<const float4*>(&Bs[kk][tx * 8 + 4]);
            float a[8] = {a0.x, a0.y, a0.z, a0.w, a1.x, a1.y, a1.z, a1.w};
            float b[8] = {b0.x, b0.y, b0.z, b0.w, b1.x, b1.y, b1.z, b1.w};
#pragma unroll
            for (int i = 0; i < 8; i++)
#pragma unroll
                for (int j = 0; j < 8; j++)
                    acc[i][j] = fmaf(a[i], b[j], acc[i][j]);
        }
        __syncthreads();
    }
    const int cRow0 = m0 + ty * 8, cCol0 = n0 + tx * 8;
#pragma unroll
    for (int i = 0; i < 8; i++) {
        int m = cRow0 + i;
        if (m >= cnt) continue;
#pragma unroll
        for (int j = 0; j < 8; j++)
            C[(size_t)m * N + cCol0 + j] = gelu_erf(acc[i][j] + bias[cCol0 + j]);
    }
}

// ---------------- logits + softmax + top-2 + margin flag ----------------
__device__ __forceinline__ void logits_core(const float* __restrict__ hrow,
                                            const float* __restrict__ gw2,
                                            const float* __restrict__ gb2,
                                            float (&red)[8][NEXP],
                                            int t, bool flag_enable)
{
    float acc[NEXP];
#pragma unroll
    for (int j = 0; j < NEXP; j++) acc[j] = 0.f;
    for (int i = threadIdx.x; i < DIMH; i += 256) {
        float h = hrow[i];
        float4 w0 = *reinterpret_cast<const float4*>(gw2 + (size_t)i * NEXP);
        float4 w1 = *reinterpret_cast<const float4*>(gw2 + (size_t)i * NEXP + 4);
        acc[0] = fmaf(h, w0.x, acc[0]); acc[1] = fmaf(h, w0.y, acc[1]);
        acc[2] = fmaf(h, w0.z, acc[2]); acc[3] = fmaf(h, w0.w, acc[3]);
        acc[4] = fmaf(h, w1.x, acc[4]); acc[5] = fmaf(h, w1.y, acc[5]);
        acc[6] = fmaf(h, w1.z, acc[6]); acc[7] = fmaf(h, w1.w, acc[7]);
    }
    const int lane = threadIdx.x & 31, wid = threadIdx.x >> 5;
#pragma unroll
    for (int j = 0; j < NEXP; j++)
#pragma unroll
        for (int o = 16; o > 0; o >>= 1)
            acc[j] += __shfl_down_sync(0xffffffffu, acc[j], o);
    if (lane == 0) {
#pragma unroll
        for (int j = 0; j < NEXP; j++) red[wid][j] = acc[j];
    }
    __syncthreads();
    if (threadIdx.x == 0) {
        float l[NEXP];
#pragma unroll
        for (int j = 0; j < NEXP; j++) {
            l[j] = gb2[j];
#pragma unroll
            for (int w = 0; w < 8; w++) l[j] += red[w][j];
        }
        float mx = l[0];
#pragma unroll
        for (int j = 1; j < NEXP; j++) mx = fmaxf(mx, l[j]);
        float p[NEXP], s = 0.f;
#pragma unroll
        for (int j = 0; j < NEXP; j++) { p[j] = expf(l[j] - mx); s += p[j]; }
        float inv = 1.0f / s;
#pragma unroll
        for (int j = 0; j < NEXP; j++) p[j] *= inv;
        int i0 = 0;
#pragma unroll
        for (int j = 1; j < NEXP; j++) if (p[j] > p[i0]) i0 = j;
        int i1 = (i0 == 0) ? 1 : 0;
#pragma unroll
        for (int j = 0; j < NEXP; j++) if (j != i0 && p[j] > p[i1]) i1 = j;
        g_topk_idx[t * 2 + 0] = i0;  g_topk_w[t * 2 + 0] = p[i0];
        g_topk_idx[t * 2 + 1] = i1;  g_topk_w[t * 2 + 1] = p[i1];
        if (flag_enable) {
            float p2 = -1.f;
#pragma unroll
            for (int j = 0; j < NEXP; j++)
                if (j != i0 && j != i1 && p[j] > p2) p2 = p[j];
            if (p[i1] - p2 < MARGIN_TAU) {
                int ix = atomicAdd(&g_fixCnt, 1);
                g_fixList[ix] = t;
            }
        }
    }
    __syncthreads();
}

__global__ void logits_topk(const float* __restrict__ h1,
                            const float* __restrict__ gw2,
                            const float* __restrict__ gb2)
{
    __shared__ float red[8][NEXP];
    const int t = blockIdx.x;
    logits_core(h1 + (size_t)t * DIMH, gw2, gb2, red, t, true);
}

__global__ void repair_logits(const float* __restrict__ hf,
                              const float* __restrict__ gw2,
                              const float* __restrict__ gb2)
{
    __shared__ float red[8][NEXP];
    for (int r = blockIdx.x; r < g_fixCnt; r += gridDim.x) {
        int t = g_fixList[r];
        logits_core(hf + (size_t)r * DIMH, gw2, gb2, red, t, false);
    }
}

// ---------------- deterministic dispatch ----------------
__global__ void dispatch_count() {
    __shared__ int scnt[NEXP];
    if (threadIdx.x < NEXP) scnt[threadIdx.x] = 0;
    __syncthreads();
    int item = blockIdx.x * 256 + threadIdx.x;
    atomicAdd(&scnt[g_topk_idx[item]], 1);
    __syncthreads();
    if (threadIdx.x < NEXP) g_blockCnt[blockIdx.x * NEXP + threadIdx.x] = scnt[threadIdx.x];
}
__global__ void dispatch_scan() {
    int e = threadIdx.x;
    if (e < NEXP) {
        int off = 0;
        for (int b = 0; b < NBLK_DISP; b++) {
            g_blockOff[b * NEXP + e] = off;
            off += g_blockCnt[b * NEXP + e];
        }
        g_cnt[e] = off;
    }
    __syncthreads();
    if (threadIdx.x == 0) {
        int base = 0, mb = 0;
        for (int i = 0; i < NEXP; i++) {
            g_base[i] = base; base += g_cnt[i];
            g_mblkBase[i] = mb; mb += (g_cnt[i] + 127) >> 7;
        }
        g_mblkBase[NEXP] = mb;
    }
}
__global__ void dispatch_write() {
    __shared__ int se[256];
    const int i = threadIdx.x;
    const int item = blockIdx.x * 256 + i;
    const int e = g_topk_idx[item];
    se[i] = e;
    __syncthreads();
    int rank = 0;
    for (int j = 0; j < i; j++) rank += (se[j] == e);
    int pos = g_base[e] + g_blockOff[blockIdx.x * NEXP + e] + rank;
    g_list[pos]  = item >> 1;
    g_wlist[pos] = g_topk_w[item];
    g_slot[item] = pos;
}

// ---------------- combine: out[t] += ho[slot0] + ho[slot1] ----------------
__global__ void combine(const float* __restrict__ ho, float* __restrict__ out) {
    const int t = blockIdx.x;
    const int c = threadIdx.x * 4;
    const int s0 = g_slot[2 * t], s1 = g_slot[2 * t + 1];
    float4 o = *reinterpret_cast<float4*>(out + (size_t)t * DIMD + c);
    float4 a = *reinterpret_cast<const float4*>(ho + (size_t)s0 * DIMD + c);
    float4 b = *reinterpret_cast<const float4*>(ho + (size_t)s1 * DIMD + c);
    o.x += a.x + b.x; o.y += a.y + b.y; o.z += a.z + b.z; o.w += a.w + b.w;
    *reinterpret_cast<float4*>(out + (size_t)t * DIMD + c) = o;
}

// ---------------- launch ----------------
extern "C" void kernel_launch(void* const* d_in, const int* in_sizes, int n_in,
                              void* d_out, int out_size)
{
    const float* x   = (const float*)d_in[0];
    const float* gw1 = (const float*)d_in[2];
    const float* gb1 = (const float*)d_in[3];
    const float* gw2 = (const float*)d_in[4];
    const float* gb2 = (const float*)d_in[5];
    const float* We1 = (const float*)d_in[6];
    const float* be1 = (const float*)d_in[7];
    const float* We2 = (const float*)d_in[8];
    const float* be2 = (const float*)d_in[9];
    const float* Ws1 = (const float*)d_in[10];
    const float* bs1 = (const float*)d_in[11];
    const float* Ws2 = (const float*)d_in[12];
    const float* bs2 = (const float*)d_in[13];
    float* out = (float*)d_out;

    float  *h1, *ho;
    __half *hs, *he, *xhi, *Bg1h, *Bs1h, *Bs2h, *Be1h, *Be2h;
    cudaGetSymbolAddress((void**)&h1,   g_h1);
    cudaGetSymbolAddress((void**)&ho,   g_ho);
    cudaGetSymbolAddress((void**)&hs,   g_hs);
    cudaGetSymbolAddress((void**)&he,   g_he);
    cudaGetSymbolAddress((void**)&xhi,  g_xhi);
    cudaGetSymbolAddress((void**)&Bg1h, g_Bg1h);
    cudaGetSymbolAddress((void**)&Bs1h, g_Bs1h);
    cudaGetSymbolAddress((void**)&Bs2h, g_Bs2h);
    cudaGetSymbolAddress((void**)&Be1h, g_Be1h);
    cudaGetSymbolAddress((void**)&Be2h, g_Be2h);

    cudaFuncSetAttribute(gemm_f16<0,1,0>, cudaFuncAttributeMaxDynamicSharedMemorySize, SME_BYTES);
    cudaFuncSetAttribute(gemm_f16<0,2,1>, cudaFuncAttributeMaxDynamicSharedMemorySize, SME_BYTES);
    cudaFuncSetAttribute(gemm_f16<0,0,0>, cudaFuncAttributeMaxDynamicSharedMemorySize, SME_BYTES);
    cudaFuncSetAttribute(gemm_f16<1,2,1>, cudaFuncAttributeMaxDynamicSharedMemorySize, SME_BYTES);
    cudaFuncSetAttribute(gemm_f16<2,0,3>, cudaFuncAttributeMaxDynamicSharedMemorySize, SME_BYTES);

    dim3 t32(32, 8);
    // launches ordered so ncu (-s 5 -c 1) captures launch #5 = dense shared-expert GEMM1
    cvt_hi<<<(T_TOK * DIMD / 4 + 255) / 256, 256>>>(x, xhi, T_TOK * DIMD / 4);              // 0 (also resets fixCnt)
    transpose_cvt<<<dim3(DIMH / 32, DIMD / 32, 1), t32>>>(gw1, Bg1h, DIMD, DIMH);           // 1
    transpose_cvt<<<dim3(DIMH / 32, DIMD / 32, 1), t32>>>(Ws1, Bs1h, DIMD, DIMH);           // 2
    transpose_cvt<<<dim3(DIMD / 32, DIMH / 32, 1), t32>>>(Ws2, Bs2h, DIMH, DIMD);           // 3
    gemm_f16<0,1,0><<<dim3(T_TOK / 128, DIMH / 128), 256, SME_BYTES>>>(xhi, Bg1h, gb1, h1, DIMD, DIMH); // 4 gate
    gemm_f16<0,2,1><<<dim3(T_TOK / 128, DIMH / 128), 256, SME_BYTES>>>(xhi, Bs1h, bs1, hs, DIMD, DIMH); // 5 shared1 <- profiled
    gemm_f16<0,0,0><<<dim3(T_TOK / 128, DIMD / 128), 256, SME_BYTES>>>(hs, Bs2h, bs2, out, DIMH, DIMD); // 6 shared2
    transpose_cvt<<<dim3(DIMH / 32, DIMD / 32, NEXP), t32>>>(We1, Be1h, DIMD, DIMH);        // 7
    transpose_cvt<<<dim3(DIMD / 32, DIMH / 32, NEXP), t32>>>(We2, Be2h, DIMH, DIMD);        // 8
    // routing + margin repair
    logits_topk<<<T_TOK, 256>>>(h1, gw2, gb2);
    sgemm_fix<<<dim3(T_TOK / 128, DIMH / 128), 256>>>(x, gw1, gb1, h1);
    repair_logits<<<512, 256>>>(h1, gw2, gb2);
    // dispatch
    dispatch_count<<<NBLK_DISP, 256>>>();
    dispatch_scan<<<1, 32>>>();
    dispatch_write<<<NBLK_DISP, 256>>>();
    // routed experts
    gemm_f16<1,2,1><<<dim3(136, DIMH / 128), 256, SME_BYTES>>>(xhi, Be1h, be1, he, DIMD, DIMH);
    gemm_f16<2,0,3><<<dim3(136, DIMD / 128), 256, SME_BYTES>>>(he,  Be2h, be2, ho, DIMH, DIMD);
    combine<<<T_TOK, 256>>>(ho, out);
}

// round 7
// speedup vs baseline: 5.4065x; 1.0094x over previous
#include <cuda_runtime.h>
#include <cuda_fp16.h>
#include <cstdint>
#include <math.h>

// ---------------- problem constants ----------------
#define T_TOK 8192
#define DIMD  1024
#define DIMH  2048
#define NEXP  8
#define NITEM (T_TOK*2)
#define NBLK_DISP 64
#define MARGIN_TAU 1e-3f

// ---------------- scratch (device globals) ----------------
__device__ float  g_h1[(size_t)T_TOK * DIMH];           // gate hidden fp32; reused as repair buffer
__device__ __half g_hs[(size_t)T_TOK * DIMH];           // shared-expert hidden fp16
__device__ __half g_he[(size_t)NITEM * DIMH];           // routed hidden fp16 (compact)
__device__ float  g_ho[(size_t)NITEM * DIMD];           // routed out rows (weighted, compact)
__device__ __half g_xhi[(size_t)T_TOK * DIMD];
__device__ __half g_Bg1h[(size_t)DIMD * DIMH];          // gw1 fp16 (row-major [K,N])
__device__ __half g_Bs1h[(size_t)DIMD * DIMH];          // Ws1 fp16
__device__ __half g_Bs2h[(size_t)DIMH * DIMD];          // Ws2 fp16
__device__ __half g_Be1h[(size_t)NEXP * DIMD * DIMH];   // We1 fp16
__device__ __half g_Be2h[(size_t)NEXP * DIMH * DIMD];   // We2 fp16
__device__ int    g_topk_idx[NITEM];
__device__ float  g_topk_w[NITEM];
__device__ int    g_list[NITEM];
__device__ float  g_wlist[NITEM];
__device__ int    g_slot[NITEM];                        // item -> compact slot
__device__ int    g_cnt[NEXP];
__device__ int    g_base[NEXP];
__device__ int    g_mblkBase[NEXP + 1];
__device__ int    g_blockCnt[NBLK_DISP * NEXP];
__device__ int    g_blockOff[NBLK_DISP * NEXP];
__device__ int    g_fixCnt;
__device__ int    g_fixList[T_TOK];

// ---------------- small helpers (defined BEFORE use) ----------------
__device__ __forceinline__ uint32_t h2_as_u32(__half2 h) {
    return *reinterpret_cast<uint32_t*>(&h);
}
__device__ __forceinline__ uint32_t smem_u32(const void* p) {
    uint32_t a;
    asm("{ .reg .u64 t; cvta.to.shared.u64 t, %1; cvt.u32.u64 %0, t; }" : "=r"(a) : "l"(p));
    return a;
}
__device__ __forceinline__ void ldsm4(uint32_t& r0, uint32_t& r1, uint32_t& r2, uint32_t& r3, uint32_t a) {
    asm volatile("ldmatrix.sync.aligned.m8n8.x4.shared.b16 {%0,%1,%2,%3}, [%4];"
                 : "=r"(r0), "=r"(r1), "=r"(r2), "=r"(r3) : "r"(a));
}
__device__ __forceinline__ void ldsm4t(uint32_t& r0, uint32_t& r1, uint32_t& r2, uint32_t& r3, uint32_t a) {
    asm volatile("ldmatrix.sync.aligned.m8n8.x4.trans.shared.b16 {%0,%1,%2,%3}, [%4];"
                 : "=r"(r0), "=r"(r1), "=r"(r2), "=r"(r3) : "r"(a));
}
__device__ __forceinline__ void mma16816(float* d, const uint32_t* a, const uint32_t* b) {
    asm volatile("mma.sync.aligned.m16n8k16.row.col.f32.f16.f16.f32 "
                 "{%0,%1,%2,%3},{%4,%5,%6,%7},{%8,%9},{%0,%1,%2,%3};"
                 : "+f"(d[0]), "+f"(d[1]), "+f"(d[2]), "+f"(d[3])
                 : "r"(a[0]), "r"(a[1]), "r"(a[2]), "r"(a[3]), "r"(b[0]), "r"(b[1]));
}
#define CP_ASYNC16(sa, ga) asm volatile("cp.async.cg.shared.global [%0], [%1], 16;" :: "r"(sa), "l"(ga))
#define CP_COMMIT()        asm volatile("cp.async.commit_group;" ::: "memory")
template<int N> __device__ __forceinline__ void cp_wait() {
    asm volatile("cp.async.wait_group %0;" :: "n"(N) : "memory");
}

// ---------------- activations ----------------
__device__ __forceinline__ float gelu_erf(float v) {
    return 0.5f * v * (1.0f + erff(v * 0.70710678118654752f));
}
__device__ __forceinline__ float gelu_tanh(float v) {
    float u = 0.7978845608028654f * (v + 0.044715f * v * v * v);
    float t = __expf(2.0f * u);
    float th = 1.0f - __fdividef(2.0f, t + 1.0f);
    return 0.5f * v * (1.0f + th);
}

// ---------------- conversions (pure streaming, no transpose) ----------------
__global__ void cvt_hi(const float* __restrict__ src, __half* __restrict__ hi, int n8) {
    int i = blockIdx.x * blockDim.x + threadIdx.x;
    if (i == 0) g_fixCnt = 0;                           // fused reset
    if (i >= n8) return;
    float4 v0 = reinterpret_cast<const float4*>(src)[2 * i];
    float4 v1 = reinterpret_cast<const float4*>(src)[2 * i + 1];
    uint4 o;
    o.x = h2_as_u32(__halves2half2(__float2half_rn(v0.x), __float2half_rn(v0.y)));
    o.y = h2_as_u32(__halves2half2(__float2half_rn(v0.z), __float2half_rn(v0.w)));
    o.z = h2_as_u32(__halves2half2(__float2half_rn(v1.x), __float2half_rn(v1.y)));
    o.w = h2_as_u32(__halves2half2(__float2half_rn(v1.z), __float2half_rn(v1.w)));
    reinterpret_cast<uint4*>(hi)[i] = o;
}

__global__ void cvt_w(const float* __restrict__ src, __half* __restrict__ dst, int n8) {
    int i = blockIdx.x * blockDim.x + threadIdx.x;
    if (i >= n8) return;
    float4 v0 = reinterpret_cast<const float4*>(src)[2 * i];
    float4 v1 = reinterpret_cast<const float4*>(src)[2 * i + 1];
    uint4 o;
    o.x = h2_as_u32(__halves2half2(__float2half_rn(v0.x), __float2half_rn(v0.y)));
    o.y = h2_as_u32(__halves2half2(__float2half_rn(v0.z), __float2half_rn(v0.w)));
    o.z = h2_as_u32(__halves2half2(__float2half_rn(v1.x), __float2half_rn(v1.y)));
    o.w = h2_as_u32(__halves2half2(__float2half_rn(v1.z), __float2half_rn(v1.w)));
    reinterpret_cast<uint4*>(dst)[i] = o;
}

// ---------------- fp16 tensor GEMM: CTA 128x128, BK=64, 3-stage cp.async ----------------
// A row-major [M,K] (ldsm non-trans); B row-major [K,N] (ldsm.trans, no weight transpose needed)
// MODE 0: dense A rows; 1: gather A rows via g_list (expert blocks); 2: dense compact A
// ACT 0: none, 1: gelu_erf, 2: gelu_tanh
// OUT 0: fp32 store; 1: fp16 store; 3: weighted fp32 store to compact row (base+m);
//     4: fp32 store + fused routed combine (out = v + ho[slot0] + ho[slot1])
#define ROWPAD_A 144                  // bytes per A smem row
#define ROWPAD_B 272                  // bytes per B smem row (64 k-rows x 272B)
#define TILE_A (128 * ROWPAD_A)       // 18432 B
#define TILE_B (64 * ROWPAD_B)        // 17408 B
#define STAGE_E (TILE_A + TILE_B)     // 35840 B
#define SME_BYTES (3 * STAGE_E)       // 107520 B

template<int MODE, int ACT, int OUT>
__global__ __launch_bounds__(256, 2)
void gemm_f16(const __half* __restrict__ A, const __half* __restrict__ B,
              const float* __restrict__ bias, void* __restrict__ Cv,
              int K, int ldn)
{
    int e = 0, m0, base = 0, cnt = 0;
    if (MODE == 0) {
        m0 = blockIdx.x * 128;
    } else {
        if ((int)blockIdx.x >= g_mblkBase[NEXP]) return;
#pragma unroll
        for (int i = 1; i < NEXP; i++) if ((int)blockIdx.x >= g_mblkBase[i]) e = i;
        m0 = ((int)blockIdx.x - g_mblkBase[e]) * 128;
        base = g_base[e]; cnt = g_cnt[e];
        B    += (size_t)e * K * ldn;
        bias += (size_t)e * ldn;
    }
    const int n0 = blockIdx.y * 128;

    extern __shared__ char smem[];
    const uint32_t sbase = smem_u32(smem);
    const int tid = threadIdx.x, lane = tid & 31, wid = tid >> 5;

    // A loads: thread covers rows tid>>3 (+32i), 16B chunk col tid&7
    const int larow = tid >> 3;
    const uint32_t dstA = (uint32_t)(larow * ROWPAD_A + (tid & 7) * 16);
    const __half* aptr[4];
#pragma unroll
    for (int i = 0; i < 4; i++) {
        int m = m0 + larow + 32 * i;
        if (MODE == 0)      aptr[i] = A + (size_t)m * K;
        else if (MODE == 1) { int mm = (m < cnt) ? m : 0; aptr[i] = A + (size_t)g_list[base + mm] * K; }
        else                { int mm = (m < cnt) ? m : 0; aptr[i] = A + (size_t)(base + mm) * K; }
        aptr[i] += (tid & 7) * 8;
    }
    // B loads: thread covers k-rows tid>>4 (+16i), 16B chunk col tid&15
    const int lbrow = tid >> 4;
    const uint32_t dstB = (uint32_t)(lbrow * ROWPAD_B + (tid & 15) * 16);
    const __half* bptr[4];
#pragma unroll
    for (int i = 0; i < 4; i++)
        bptr[i] = B + (size_t)(lbrow + 16 * i) * ldn + n0 + (tid & 15) * 8;

    const int S = K >> 6;
    auto issue = [&](int s) {
        uint32_t st = sbase + (uint32_t)((s % 3) * STAGE_E);
#pragma unroll
        for (int i = 0; i < 4; i++)
            CP_ASYNC16(st + dstA + (uint32_t)(32 * i * ROWPAD_A), (const void*)(aptr[i] + s * 64));
#pragma unroll
        for (int i = 0; i < 4; i++)
            CP_ASYNC16(st + TILE_A + dstB + (uint32_t)(16 * i * ROWPAD_B), (const void*)(bptr[i] + (size_t)s * 64 * ldn));
        CP_COMMIT();
    };
    issue(0);
    if (S > 1) issue(1);

    const int wm0 = (wid >> 1) * 32;
    const int wn0 = (wid & 1) * 64;
    const int arow_l = (lane & 7) + ((lane >> 3) & 1) * 8;
    const int acol_l = (lane >> 4) * 8;
    // B trans-lane map: k-offset = (lane&7) + 8*((lane>>3)&1), n-offset = 8*(lane>>4)
    const int bkrow_l = (lane & 7) + ((lane >> 3) & 1) * 8;
    const int bncol_l = (lane >> 4) * 8;

    float acc[2][8][4];
#pragma unroll
    for (int i = 0; i < 2; i++)
#pragma unroll
        for (int j = 0; j < 8; j++)
#pragma unroll
            for (int q = 0; q < 4; q++) acc[i][j][q] = 0.f;

    // single-barrier mainloop: wait -> sync -> prefetch(s+2) -> compute(s)
    for (int s = 0; s < S; s++) {
        if (s + 1 < S) cp_wait<1>(); else cp_wait<0>();
        __syncthreads();
        if (s + 2 < S) issue(s + 2);

        const uint32_t st = sbase + (uint32_t)((s % 3) * STAGE_E);
        const uint32_t sA = st, sB = st + TILE_A;
#pragma unroll
        for (int ks = 0; ks < 4; ks++) {
            const int k0 = ks * 16;
            uint32_t a[2][4], b[4][4];
#pragma unroll
            for (int mf = 0; mf < 2; mf++)
                ldsm4(a[mf][0], a[mf][1], a[mf][2], a[mf][3],
                      sA + (uint32_t)((wm0 + mf * 16 + arow_l) * ROWPAD_A + (k0 + acol_l) * 2));
#pragma unroll
            for (int p = 0; p < 4; p++)
                ldsm4t(b[p][0], b[p][1], b[p][2], b[p][3],
                       sB + (uint32_t)((k0 + bkrow_l) * ROWPAD_B + (wn0 + p * 16 + bncol_l) * 2));
#pragma unroll
            for (int mf = 0; mf < 2; mf++)
#pragma unroll
                for (int nf = 0; nf < 8; nf++)
                    mma16816(acc[mf][nf], a[mf], &b[nf >> 1][(nf & 1) * 2]);
        }
    }

    // ---- epilogue ----
    const int tr = lane >> 2, tc = (lane & 3) * 2;
#pragma unroll
    for (int mf = 0; mf < 2; mf++) {
#pragma unroll
        for (int half_ = 0; half_ < 2; half_++) {
            const int m = m0 + wm0 + mf * 16 + tr + half_ * 8;
            bool ok = (MODE == 0) || (m < cnt);
            if (!ok) continue;
            int orow = m; float wgt = 1.f;
            int s0 = 0, s1 = 0;
            if (MODE == 1) orow = base + m;
            if (MODE == 2) {
                if (OUT == 3) { orow = base + m; wgt = g_wlist[base + m]; }
                else          { orow = g_list[base + m]; wgt = g_wlist[base + m]; }
            }
            if (OUT == 4) { s0 = g_slot[2 * m]; s1 = g_slot[2 * m + 1]; }
#pragma unroll
            for (int nf = 0; nf < 8; nf++) {
                const int c = n0 + wn0 + nf * 8 + tc;
                float v0 = acc[mf][nf][half_ * 2 + 0] + bias[c];
                float v1 = acc[mf][nf][half_ * 2 + 1] + bias[c + 1];
                if (ACT == 1) { v0 = gelu_erf(v0);  v1 = gelu_erf(v1); }
                if (ACT == 2) { v0 = gelu_tanh(v0); v1 = gelu_tanh(v1); }
                if (OUT == 0) {
                    float2 w2; w2.x = v0; w2.y = v1;
                    *reinterpret_cast<float2*>((float*)Cv + (size_t)orow * ldn + c) = w2;
                } else if (OUT == 1) {
                    *reinterpret_cast<__half2*>((__half*)Cv + (size_t)orow * ldn + c) =
                        __halves2half2(__float2half_rn(v0), __float2half_rn(v1));
                } else if (OUT == 3) {
                    float2 w2; w2.x = wgt * v0; w2.y = wgt * v1;
                    *reinterpret_cast<float2*>((float*)Cv + (size_t)orow * ldn + c) = w2;
                } else { // OUT == 4: fused routed combine
                    float2 r0 = *reinterpret_cast<const float2*>(g_ho + (size_t)s0 * DIMD + c);
                    float2 r1 = *reinterpret_cast<const float2*>(g_ho + (size_t)s1 * DIMD + c);
                    float2 w2; w2.x = v0 + r0.x + r1.x; w2.y = v1 + r0.y + r1.y;
                    *reinterpret_cast<float2*>((float*)Cv + (size_t)orow * ldn + c) = w2;
                }
            }
        }
    }
}

// ---------------- fp32 repair SGEMM: gathered rows (g_fixList), gelu_erf, compact out ----------------
__global__ __launch_bounds__(256, 2)
void sgemm_fix(const float* __restrict__ A, const float* __restrict__ B,
               const float* __restrict__ bias, float* __restrict__ C)
{
    const int cnt = g_fixCnt;
    const int m0 = blockIdx.x * 128;
    if (m0 >= cnt) return;
    const int n0 = blockIdx.y * 128;
    const int K = DIMD, N = DIMH;

    __shared__ float As[8][128];
    __shared__ float Bs[8][128];
    const int tid = threadIdx.x;
    const int aRow = tid >> 1, aCol = (tid & 1) * 4;
    const int bRow = tid >> 5, bCol = (tid & 31) * 4;

    int mA = m0 + aRow;
    int mm = (mA < cnt) ? mA : 0;
    const float* Arow = A + (size_t)g_fixList[mm] * K;
    const float* Bp = B + (size_t)bRow * N + n0 + bCol;

    const int ty = tid >> 4, tx = tid & 15;
    float acc[8][8];
#pragma unroll
    for (int i = 0; i < 8; i++)
#pragma unroll
        for (int j = 0; j < 8; j++) acc[i][j] = 0.f;

    for (int k0 = 0; k0 < K; k0 += 8) {
        float4 av = *reinterpret_cast<const float4*>(Arow + k0 + aCol);
        As[aCol + 0][aRow] = av.x; As[aCol + 1][aRow] = av.y;
        As[aCol + 2][aRow] = av.z; As[aCol + 3][aRow] = av.w;
        *reinterpret_cast<float4*>(&Bs[bRow][bCol]) = *reinterpret_cast<const float4*>(Bp + (size_t)k0 * N);
        __syncthreads();
#pragma unroll
        for (int kk = 0; kk < 8; kk++) {
            float4 a0 = *reinterpret_cast<const float4*>(&As[kk][ty * 8]);
            float4 a1 = *reinterpret_cast<const float4*>(&As[kk][ty * 8 + 4]);
            float4 b0 = *reinterpret_cast<const float4*>(&Bs[kk][tx * 8]);
            float4 b1 = *reinterpret_cast<const float4*>(&Bs[kk][tx * 8 + 4]);
            float a[8] = {a0.x, a0.y, a0.z, a0.w, a1.x, a1.y, a1.z, a1.w};
            float b[8] = {b0.x, b0.y, b0.z, b0.w, b1.x, b1.y, b1.z, b1.w};
#pragma unroll
            for (int i = 0; i < 8; i++)
#pragma unroll
                for (int j = 0; j < 8; j++)
                    acc[i][j] = fmaf(a[i], b[j], acc[i][j]);
        }
        __syncthreads();
    }
    const int cRow0 = m0 + ty * 8, cCol0 = n0 + tx * 8;
#pragma unroll
    for (int i = 0; i < 8; i++) {
        int m = cRow0 + i;
        if (m >= cnt) continue;
#pragma unroll
        for (int j = 0; j < 8; j++)
            C[(size_t)m * N + cCol0 + j] = gelu_erf(acc[i][j] + bias[cCol0 + j]);
    }
}

// ---------------- logits + softmax + top-2 + margin flag ----------------
__device__ __forceinline__ void logits_core(const float* __restrict__ hrow,
                                            const float* __restrict__ gw2,
                                            const float* __restrict__ gb2,
                                            float (&red)[8][NEXP],
                                            int t, bool flag_enable)
{
    float acc[NEXP];
#pragma unroll
    for (int j = 0; j < NEXP; j++) acc[j] = 0.f;
    for (int i = threadIdx.x; i < DIMH; i += 256) {
        float h = hrow[i];
        float4 w0 = *reinterpret_cast<const float4*>(gw2 + (size_t)i * NEXP);
        float4 w1 = *reinterpret_cast<const float4*>(gw2 + (size_t)i * NEXP + 4);
        acc[0] = fmaf(h, w0.x, acc[0]); acc[1] = fmaf(h, w0.y, acc[1]);
        acc[2] = fmaf(h, w0.z, acc[2]); acc[3] = fmaf(h, w0.w, acc[3]);
        acc[4] = fmaf(h, w1.x, acc[4]); acc[5] = fmaf(h, w1.y, acc[5]);
        acc[6] = fmaf(h, w1.z, acc[6]); acc[7] = fmaf(h, w1.w, acc[7]);
    }
    const int lane = threadIdx.x & 31, wid = threadIdx.x >> 5;
#pragma unroll
    for (int j = 0; j < NEXP; j++)
#pragma unroll
        for (int o = 16; o > 0; o >>= 1)
            acc[j] += __shfl_down_sync(0xffffffffu, acc[j], o);
    if (lane == 0) {
#pragma unroll
        for (int j = 0; j < NEXP; j++) red[wid][j] = acc[j];
    }
    __syncthreads();
    if (threadIdx.x == 0) {
        float l[NEXP];
#pragma unroll
        for (int j = 0; j < NEXP; j++) {
            l[j] = gb2[j];
#pragma unroll
            for (int w = 0; w < 8; w++) l[j] += red[w][j];
        }
        float mx = l[0];
#pragma unroll
        for (int j = 1; j < NEXP; j++) mx = fmaxf(mx, l[j]);
        float p[NEXP], s = 0.f;
#pragma unroll
        for (int j = 0; j < NEXP; j++) { p[j] = expf(l[j] - mx); s += p[j]; }
        float inv = 1.0f / s;
#pragma unroll
        for (int j = 0; j < NEXP; j++) p[j] *= inv;
        int i0 = 0;
#pragma unroll
        for (int j = 1; j < NEXP; j++) if (p[j] > p[i0]) i0 = j;
        int i1 = (i0 == 0) ? 1 : 0;
#pragma unroll
        for (int j = 0; j < NEXP; j++) if (j != i0 && p[j] > p[i1]) i1 = j;
        g_topk_idx[t * 2 + 0] = i0;  g_topk_w[t * 2 + 0] = p[i0];
        g_topk_idx[t * 2 + 1] = i1;  g_topk_w[t * 2 + 1] = p[i1];
        if (flag_enable) {
            float p2 = -1.f;
#pragma unroll
            for (int j = 0; j < NEXP; j++)
                if (j != i0 && j != i1 && p[j] > p2) p2 = p[j];
            if (p[i1] - p2 < MARGIN_TAU) {
                int ix = atomicAdd(&g_fixCnt, 1);
                g_fixList[ix] = t;
            }
        }
    }
    __syncthreads();
}

__global__ void logits_topk(const float* __restrict__ h1,
                            const float* __restrict__ gw2,
                            const float* __restrict__ gb2)
{
    __shared__ float red[8][NEXP];
    const int t = blockIdx.x;
    logits_core(h1 + (size_t)t * DIMH, gw2, gb2, red, t, true);
}

__global__ void repair_logits(const float* __restrict__ hf,
                              const float* __restrict__ gw2,
                              const float* __restrict__ gb2)
{
    __shared__ float red[8][NEXP];
    for (int r = blockIdx.x; r < g_fixCnt; r += gridDim.x) {
        int t = g_fixList[r];
        logits_core(hf + (size_t)r * DIMH, gw2, gb2, red, t, false);
    }
}

// ---------------- deterministic dispatch ----------------
__global__ void dispatch_count() {
    __shared__ int scnt[NEXP];
    if (threadIdx.x < NEXP) scnt[threadIdx.x] = 0;
    __syncthreads();
    int item = blockIdx.x * 256 + threadIdx.x;
    atomicAdd(&scnt[g_topk_idx[item]], 1);
    __syncthreads();
    if (threadIdx.x < NEXP) g_blockCnt[blockIdx.x * NEXP + threadIdx.x] = scnt[threadIdx.x];
}
__global__ void dispatch_scan() {
    int e = threadIdx.x;
    if (e < NEXP) {
        int off = 0;
        for (int b = 0; b < NBLK_DISP; b++) {
            g_blockOff[b * NEXP + e] = off;
            off += g_blockCnt[b * NEXP + e];
        }
        g_cnt[e] = off;
    }
    __syncthreads();
    if (threadIdx.x == 0) {
        int base = 0, mb = 0;
        for (int i = 0; i < NEXP; i++) {
            g_base[i] = base; base += g_cnt[i];
            g_mblkBase[i] = mb; mb += (g_cnt[i] + 127) >> 7;
        }
        g_mblkBase[NEXP] = mb;
    }
}
__global__ void dispatch_write() {
    __shared__ int se[256];
    const int i = threadIdx.x;
    const int item = blockIdx.x * 256 + i;
    const int e = g_topk_idx[item];
    se[i] = e;
    __syncthreads();
    int rank = 0;
    for (int j = 0; j < i; j++) rank += (se[j] == e);
    int pos = g_base[e] + g_blockOff[blockIdx.x * NEXP + e] + rank;
    g_list[pos]  = item >> 1;
    g_wlist[pos] = g_topk_w[item];
    g_slot[item] = pos;
}

// ---------------- launch ----------------
extern "C" void kernel_launch(void* const* d_in, const int* in_sizes, int n_in,
                              void* d_out, int out_size)
{
    const float* x   = (const float*)d_in[0];
    const float* gw1 = (const float*)d_in[2];
    const float* gb1 = (const float*)d_in[3];
    const float* gw2 = (const float*)d_in[4];
    const float* gb2 = (const float*)d_in[5];
    const float* We1 = (const float*)d_in[6];
    const float* be1 = (const float*)d_in[7];
    const float* We2 = (const float*)d_in[8];
    const float* be2 = (const float*)d_in[9];
    const float* Ws1 = (const float*)d_in[10];
    const float* bs1 = (const float*)d_in[11];
    const float* Ws2 = (const float*)d_in[12];
    const float* bs2 = (const float*)d_in[13];
    float* out = (float*)d_out;

    float  *h1, *ho;
    __half *hs, *he, *xhi, *Bg1h, *Bs1h, *Bs2h, *Be1h, *Be2h;
    cudaGetSymbolAddress((void**)&h1,   g_h1);
    cudaGetSymbolAddress((void**)&ho,   g_ho);
    cudaGetSymbolAddress((void**)&hs,   g_hs);
    cudaGetSymbolAddress((void**)&he,   g_he);
    cudaGetSymbolAddress((void**)&xhi,  g_xhi);
    cudaGetSymbolAddress((void**)&Bg1h, g_Bg1h);
    cudaGetSymbolAddress((void**)&Bs1h, g_Bs1h);
    cudaGetSymbolAddress((void**)&Bs2h, g_Bs2h);
    cudaGetSymbolAddress((void**)&Be1h, g_Be1h);
    cudaGetSymbolAddress((void**)&Be2h, g_Be2h);

    cudaFuncSetAttribute(gemm_f16<0,1,0>, cudaFuncAttributeMaxDynamicSharedMemorySize, SME_BYTES);
    cudaFuncSetAttribute(gemm_f16<0,2,1>, cudaFuncAttributeMaxDynamicSharedMemorySize, SME_BYTES);
    cudaFuncSetAttribute(gemm_f16<0,0,4>, cudaFuncAttributeMaxDynamicSharedMemorySize, SME_BYTES);
    cudaFuncSetAttribute(gemm_f16<1,2,1>, cudaFuncAttributeMaxDynamicSharedMemorySize, SME_BYTES);
    cudaFuncSetAttribute(gemm_f16<2,0,3>, cudaFuncAttributeMaxDynamicSharedMemorySize, SME_BYTES);

    // ---- prep: streaming fp32->fp16 converts (no transposes) ----
    cvt_hi<<<(T_TOK * DIMD / 8 + 255) / 256, 256>>>(x, xhi, T_TOK * DIMD / 8);
    cvt_w<<<(DIMD * DIMH / 8 + 255) / 256, 256>>>(gw1, Bg1h, DIMD * DIMH / 8);
    // gate hidden single-pass fp16, fp32 out
    gemm_f16<0,1,0><<<dim3(T_TOK / 128, DIMH / 128), 256, SME_BYTES>>>(xhi, Bg1h, gb1, h1, DIMD, DIMH);
    cvt_w<<<(DIMD * DIMH / 8 + 255) / 256, 256>>>(Ws1, Bs1h, DIMD * DIMH / 8);
    cvt_w<<<(DIMH * DIMD / 8 + 255) / 256, 256>>>(Ws2, Bs2h, DIMH * DIMD / 8);
    cvt_w<<<(NEXP * DIMD * DIMH / 8 + 255) / 256, 256>>>(We1, Be1h, NEXP * DIMD * DIMH / 8);
    cvt_w<<<(NEXP * DIMH * DIMD / 8 + 255) / 256, 256>>>(We2, Be2h, NEXP * DIMH * DIMD / 8);
    // routing + margin repair
    logits_topk<<<T_TOK, 256>>>(h1, gw2, gb2);
    sgemm_fix<<<dim3(T_TOK / 128, DIMH / 128), 256>>>(x, gw1, gb1, h1);
    repair_logits<<<512, 256>>>(h1, gw2, gb2);
    // dispatch
    dispatch_count<<<NBLK_DISP, 256>>>();
    dispatch_scan<<<1, 32>>>();
    dispatch_write<<<NBLK_DISP, 256>>>();
    // routed experts first (so shared2 can fuse the combine)
    gemm_f16<1,2,1><<<dim3(136, DIMH / 128), 256, SME_BYTES>>>(xhi, Be1h, be1, he, DIMD, DIMH);
    gemm_f16<2,0,3><<<dim3(136, DIMD / 128), 256, SME_BYTES>>>(he,  Be2h, be2, ho, DIMH, DIMD);
    // shared expert; GEMM2 epilogue fuses routed combine
    gemm_f16<0,2,1><<<dim3(T_TOK / 128, DIMH / 128), 256, SME_BYTES>>>(xhi, Bs1h, bs1, hs,  DIMD, DIMH);
    gemm_f16<0,0,4><<<dim3(T_TOK / 128, DIMD / 128), 256, SME_BYTES>>>(hs,  Bs2h, bs2, out, DIMH, DIMD);
}